// round 1
// baseline (speedup 1.0000x reference)
#include <cuda_runtime.h>
#include <cstdint>
#include <cstddef>

#define D_MODELC 1024
#define NHEADC   16
#define DKC      64
#define SEQC     2048
#define BATCHC   2

// ---------------- device scratch (allocation-free) ----------------
__device__ float g_Q[BATCHC * NHEADC * SEQC * DKC];     // [b,h,s,dk]
__device__ float g_K[BATCHC * NHEADC * SEQC * DKC];
__device__ float g_V[BATCHC * NHEADC * SEQC * DKC];
__device__ float g_ctx[BATCHC * SEQC * D_MODELC];       // [b,s,h*64+dk]
__device__ int   g_flags[BATCHC * 32 * 32];             // per (b,qtile,ktile) mask flag

// ---------------- fast exp on the FMA pipe (avoids MUFU bottleneck) ----------------
__device__ __forceinline__ float fast_exp(float x) {
    x = fmaxf(x, -87.0f);
    float t  = fmaf(x, 1.4426950408889634f, 12582912.0f);   // round(x*log2e) via magic
    int   n  = __float_as_int(t) - 0x4B400000;
    float fn = t - 12582912.0f;
    float f  = fmaf(fn, -0.693359375f, x);                  // Cody-Waite hi
    f        = fmaf(fn,  2.12194899e-4f, f);                // Cody-Waite lo
    float p  = 8.33333377e-3f;                              // 1/120
    p = fmaf(p, f, 4.16666679e-2f);                         // 1/24
    p = fmaf(p, f, 0.16666667f);
    p = fmaf(p, f, 0.5f);
    p = fmaf(p, f, 1.0f);
    p = fmaf(p, f, 1.0f);
    return __int_as_float(__float_as_int(p) + (n << 23));
}

// ---------------- mask prescan: one flag per (b, 64q-tile, 64k-tile) ----------------
__global__ void __launch_bounds__(256)
prescan_kernel(const unsigned char* __restrict__ am,
               const unsigned char* __restrict__ kpm,
               int* __restrict__ flags)
{
    const int kt = blockIdx.x, qt = blockIdx.y, b = blockIdx.z;
    const int tid = threadIdx.x;
    unsigned v = 0;
    {
        int q = qt * 64 + (tid >> 2);
        const uint4* p = (const uint4*)(am + ((size_t)(b * SEQC + q)) * SEQC + kt * 64) + (tid & 3);
        uint4 u = *p;
        v = u.x | u.y | u.z | u.w;
    }
    if (tid < 4) {
        const uint4* p = (const uint4*)(kpm + (size_t)b * SEQC + kt * 64) + tid;
        uint4 u = *p;
        v |= u.x | u.y | u.z | u.w;
    }
    #pragma unroll
    for (int off = 16; off >= 1; off >>= 1)
        v |= __shfl_xor_sync(0xffffffffu, v, off);
    __shared__ unsigned wv[8];
    if ((tid & 31) == 0) wv[tid >> 5] = v;
    __syncthreads();
    if (tid == 0) {
        unsigned r = 0;
        #pragma unroll
        for (int w = 0; w < 8; ++w) r |= wv[w];
        flags[(b * 32 + qt) * 32 + kt] = r ? 1 : 0;
    }
}

// ---------------- Y = X @ W^T + b (64x64 tile, 4x4 register blocking) ----------------
// split_heads=1: Y layout [b,h,s,dk]; split_heads=0: Y layout [m, n] plain.
__global__ void __launch_bounds__(256)
gemm_bias_kernel(const float* __restrict__ X, const float* __restrict__ W,
                 const float* __restrict__ bias, float* __restrict__ Y,
                 int M, int N, int K, int split_heads)
{
    __shared__ __align__(16) float sX[16][64];
    __shared__ __align__(16) float sW[16][64];
    const int tid = threadIdx.x;
    const int tn = tid & 15, tm = tid >> 4;
    const int n0 = blockIdx.x * 64, m0 = blockIdx.y * 64;
    const int lr = tid >> 2, lk = (tid & 3) << 2;

    const float* xg = X + (size_t)(m0 + lr) * K + lk;
    const float* wg = W + (size_t)(n0 + lr) * K + lk;

    float acc[4][4] = {};
    for (int k0 = 0; k0 < K; k0 += 16) {
        float4 xa = *(const float4*)(xg + k0);
        float4 wa = *(const float4*)(wg + k0);
        __syncthreads();
        sX[lk + 0][lr] = xa.x; sX[lk + 1][lr] = xa.y; sX[lk + 2][lr] = xa.z; sX[lk + 3][lr] = xa.w;
        sW[lk + 0][lr] = wa.x; sW[lk + 1][lr] = wa.y; sW[lk + 2][lr] = wa.z; sW[lk + 3][lr] = wa.w;
        __syncthreads();
        #pragma unroll
        for (int kk = 0; kk < 16; ++kk) {
            float4 a  = *(const float4*)&sX[kk][tm * 4];
            float4 bb = *(const float4*)&sW[kk][tn * 4];
            float av[4] = {a.x, a.y, a.z, a.w};
            float bv[4] = {bb.x, bb.y, bb.z, bb.w};
            #pragma unroll
            for (int i = 0; i < 4; ++i)
                #pragma unroll
                for (int j = 0; j < 4; ++j)
                    acc[i][j] = fmaf(av[i], bv[j], acc[i][j]);
        }
    }

    float4 bv4 = *(const float4*)&bias[n0 + tn * 4];
    float bb[4] = {bv4.x, bv4.y, bv4.z, bv4.w};
    #pragma unroll
    for (int i = 0; i < 4; ++i) {
        int m = m0 + tm * 4 + i;
        float4 o;
        o.x = acc[i][0] + bb[0]; o.y = acc[i][1] + bb[1];
        o.z = acc[i][2] + bb[2]; o.w = acc[i][3] + bb[3];
        if (split_heads) {
            int b = m >> 11, s = m & 2047;
            int h = n0 >> 6;                 // BN=64 => one head per n-tile
            int dk = tn * 4;
            *(float4*)&Y[(((size_t)(b * NHEADC + h) * SEQC) + s) * DKC + dk] = o;
        } else {
            *(float4*)&Y[(size_t)m * N + n0 + tn * 4] = o;
        }
    }
}

// ---------------- flash attention, fp32, BQ=BK=64, dk=64 ----------------
__global__ void __launch_bounds__(256)
attn_kernel(const float* __restrict__ Q, const float* __restrict__ Kp,
            const float* __restrict__ Vp,
            const unsigned char* __restrict__ am,
            const unsigned char* __restrict__ kpm,
            const int* __restrict__ flags,
            float* __restrict__ ctx)
{
    __shared__ __align__(16) float sQt[DKC][64];   // [d][r], pre-scaled by 1/8
    __shared__ __align__(16) float sKP[DKC][64];   // [d][j] as K; reused as P[r][j]
    __shared__ __align__(16) float sV [64][DKC];   // [j][d]

    const int qt = blockIdx.x;          // 0..31
    const int bh = blockIdx.y;          // 0..31 = b*16+h
    const int b  = bh >> 4;
    const int h  = bh & 15;
    const int tid = threadIdx.x;
    const int tn = tid & 15, tm = tid >> 4;

    const float* Qb = Q  + ((size_t)bh * SEQC + qt * 64) * DKC;
    const float* Kb = Kp + (size_t)bh * SEQC * DKC;
    const float* Vb = Vp + (size_t)bh * SEQC * DKC;

    // load Q tile transposed + fold in 1/sqrt(dk)
    {
        int r = tid >> 2, dq = (tid & 3) << 4;
        const float4* src = (const float4*)(Qb + (size_t)r * DKC + dq);
        #pragma unroll
        for (int u = 0; u < 4; ++u) {
            float4 v4 = src[u];
            int d0 = dq + u * 4;
            sQt[d0 + 0][r] = v4.x * 0.125f;
            sQt[d0 + 1][r] = v4.y * 0.125f;
            sQt[d0 + 2][r] = v4.z * 0.125f;
            sQt[d0 + 3][r] = v4.w * 0.125f;
        }
    }

    float oacc[4][4] = {};
    float mrow[4] = {-1e30f, -1e30f, -1e30f, -1e30f};
    float lrow[4] = {};

    for (int kt = 0; kt < SEQC / 64; ++kt) {
        __syncthreads();  // (A) protect sKP/sV from previous iteration's readers
        {
            int j = tid >> 2, dq = (tid & 3) << 4;
            const float4* ks = (const float4*)(Kb + (size_t)(kt * 64 + j) * DKC + dq);
            const float4* vs = (const float4*)(Vb + (size_t)(kt * 64 + j) * DKC + dq);
            #pragma unroll
            for (int u = 0; u < 4; ++u) {
                float4 kv = ks[u];
                int d0 = dq + u * 4;
                sKP[d0 + 0][j] = kv.x; sKP[d0 + 1][j] = kv.y;
                sKP[d0 + 2][j] = kv.z; sKP[d0 + 3][j] = kv.w;
                float4 vv = vs[u];
                *(float4*)&sV[j][d0] = vv;
            }
        }
        __syncthreads();  // (B) tiles ready

        // S = (Q/8) K^T : 4x4 per thread
        float s[4][4] = {};
        #pragma unroll 16
        for (int d = 0; d < DKC; ++d) {
            float4 a  = *(const float4*)&sQt[d][tm * 4];
            float4 kk = *(const float4*)&sKP[d][tn * 4];
            float av[4] = {a.x, a.y, a.z, a.w};
            float bv[4] = {kk.x, kk.y, kk.z, kk.w};
            #pragma unroll
            for (int i = 0; i < 4; ++i)
                #pragma unroll
                for (int j = 0; j < 4; ++j)
                    s[i][j] = fmaf(av[i], bv[j], s[i][j]);
        }

        // masks (slow path only if any mask bit set in this tile)
        if (flags[(b * 32 + qt) * 32 + kt]) {
            #pragma unroll
            for (int i = 0; i < 4; ++i) {
                int qg = qt * 64 + tm * 4 + i;
                #pragma unroll
                for (int j = 0; j < 4; ++j) {
                    int kg = kt * 64 + tn * 4 + j;
                    if (am[((size_t)(b * SEQC + qg)) * SEQC + kg] | kpm[b * SEQC + kg])
                        s[i][j] = -1e30f;
                }
            }
        }

        // row max across 16-lane groups (lanes with same tm)
        float tmax[4];
        #pragma unroll
        for (int i = 0; i < 4; ++i)
            tmax[i] = fmaxf(fmaxf(s[i][0], s[i][1]), fmaxf(s[i][2], s[i][3]));
        #pragma unroll
        for (int off = 8; off >= 1; off >>= 1)
            #pragma unroll
            for (int i = 0; i < 4; ++i)
                tmax[i] = fmaxf(tmax[i], __shfl_xor_sync(0xffffffffu, tmax[i], off));

        __syncthreads();  // (C) all S reads of sKP done -> safe to write P there

        float* sPf = (float*)sKP;  // P[r][j], stride 64
        #pragma unroll
        for (int i = 0; i < 4; ++i) {
            float mn    = fmaxf(mrow[i], tmax[i]);
            float alpha = fast_exp(mrow[i] - mn);
            mrow[i] = mn;
            float ps = 0.f;
            #pragma unroll
            for (int j = 0; j < 4; ++j) {
                float p = fast_exp(s[i][j] - mn);
                if (s[i][j] <= -1e29f) p = 0.f;
                s[i][j] = p;
                ps += p;
            }
            #pragma unroll
            for (int off = 8; off >= 1; off >>= 1)
                ps += __shfl_xor_sync(0xffffffffu, ps, off);
            lrow[i] = fmaf(lrow[i], alpha, ps);
            #pragma unroll
            for (int j = 0; j < 4; ++j) {
                oacc[i][j] *= alpha;
                sPf[(tm * 4 + i) * 64 + tn * 4 + j] = s[i][j];
            }
        }
        __syncthreads();  // (D) P visible

        // O += P V : 4 rows x 4 dims per thread
        #pragma unroll 8
        for (int j = 0; j < 64; ++j) {
            float4 v4 = *(const float4*)&sV[j][tn * 4];
            #pragma unroll
            for (int i = 0; i < 4; ++i) {
                float p = sPf[(tm * 4 + i) * 64 + j];
                oacc[i][0] = fmaf(p, v4.x, oacc[i][0]);
                oacc[i][1] = fmaf(p, v4.y, oacc[i][1]);
                oacc[i][2] = fmaf(p, v4.z, oacc[i][2]);
                oacc[i][3] = fmaf(p, v4.w, oacc[i][3]);
            }
        }
    }

    // epilogue: normalize (fully-masked rows -> 0, matching the nan-fix) and store
    #pragma unroll
    for (int i = 0; i < 4; ++i) {
        float r = (lrow[i] > 0.f) ? (1.0f / lrow[i]) : 0.f;
        float4 o;
        o.x = oacc[i][0] * r; o.y = oacc[i][1] * r;
        o.z = oacc[i][2] * r; o.w = oacc[i][3] * r;
        size_t row = (size_t)b * SEQC + qt * 64 + tm * 4 + i;
        *(float4*)&ctx[row * D_MODELC + h * DKC + tn * 4] = o;
    }
}

// ---------------- launch ----------------
extern "C" void kernel_launch(void* const* d_in, const int* in_sizes, int n_in,
                              void* d_out, int out_size)
{
    const float* query = (const float*)d_in[0];
    const float* key   = (const float*)d_in[1];
    const float* value = (const float*)d_in[2];
    const unsigned char* am  = (const unsigned char*)d_in[3];
    const unsigned char* kpm = (const unsigned char*)d_in[4];
    const float* Wq = (const float*)d_in[5];
    const float* bq = (const float*)d_in[6];
    const float* Wk = (const float*)d_in[7];
    const float* bk = (const float*)d_in[8];
    const float* Wv = (const float*)d_in[9];
    const float* bv = (const float*)d_in[10];
    const float* Wo = (const float*)d_in[11];
    const float* bo = (const float*)d_in[12];
    float* out = (float*)d_out;

    float *Qp, *Kp, *Vp, *ctx; int* flags;
    cudaGetSymbolAddress((void**)&Qp,   g_Q);
    cudaGetSymbolAddress((void**)&Kp,   g_K);
    cudaGetSymbolAddress((void**)&Vp,   g_V);
    cudaGetSymbolAddress((void**)&ctx,  g_ctx);
    cudaGetSymbolAddress((void**)&flags, g_flags);

    dim3 pg(32, 32, 2);
    prescan_kernel<<<pg, 256>>>(am, kpm, flags);

    dim3 gg(16, 64);  // N/64, M/64 with M=4096, N=1024
    gemm_bias_kernel<<<gg, 256>>>(query, Wq, bq, Qp, 4096, 1024, 1024, 1);
    gemm_bias_kernel<<<gg, 256>>>(key,   Wk, bk, Kp, 4096, 1024, 1024, 1);
    gemm_bias_kernel<<<gg, 256>>>(value, Wv, bv, Vp, 4096, 1024, 1024, 1);

    dim3 ag(32, 32);  // qtiles x (b*h)
    attn_kernel<<<ag, 256>>>(Qp, Kp, Vp, am, kpm, flags, ctx);

    gemm_bias_kernel<<<gg, 256>>>(ctx, Wo, bo, out, 4096, 1024, 1024, 0);
}

// round 4
// speedup vs baseline: 1.0938x; 1.0938x over previous
#include <cuda_runtime.h>
#include <cstdint>
#include <cstddef>

#define D_MODELC 1024
#define NHEADC   16
#define DKC      64
#define SEQC     2048
#define BATCHC   2

// ---------------- device scratch (allocation-free) ----------------
__device__ float g_Q[BATCHC * NHEADC * SEQC * DKC];     // [b,h,s,dk]
__device__ float g_K[BATCHC * NHEADC * SEQC * DKC];
__device__ float g_V[BATCHC * NHEADC * SEQC * DKC];
__device__ float g_ctx[BATCHC * SEQC * D_MODELC];       // [b,s,h*64+dk]
__device__ int   g_flags[BATCHC * 32 * 32];             // per (b,64q-tile,64k-tile)

// ---------------- fast exp on the FMA pipe ----------------
__device__ __forceinline__ float fast_exp(float x) {
    x = fmaxf(x, -87.0f);
    float t  = fmaf(x, 1.4426950408889634f, 12582912.0f);
    int   n  = __float_as_int(t) - 0x4B400000;
    float fn = t - 12582912.0f;
    float f  = fmaf(fn, -0.693359375f, x);
    f        = fmaf(fn,  2.12194899e-4f, f);
    float p  = 8.33333377e-3f;
    p = fmaf(p, f, 4.16666679e-2f);
    p = fmaf(p, f, 0.16666667f);
    p = fmaf(p, f, 0.5f);
    p = fmaf(p, f, 1.0f);
    p = fmaf(p, f, 1.0f);
    return __int_as_float(__float_as_int(p) + (n << 23));
}

// ---------------- mask prescan (unchanged) ----------------
__global__ void __launch_bounds__(256)
prescan_kernel(const unsigned char* __restrict__ am,
               const unsigned char* __restrict__ kpm,
               int* __restrict__ flags)
{
    const int kt = blockIdx.x, qt = blockIdx.y, b = blockIdx.z;
    const int tid = threadIdx.x;
    unsigned v = 0;
    {
        int q = qt * 64 + (tid >> 2);
        const uint4* p = (const uint4*)(am + ((size_t)(b * SEQC + q)) * SEQC + kt * 64) + (tid & 3);
        uint4 u = *p;
        v = u.x | u.y | u.z | u.w;
    }
    if (tid < 4) {
        const uint4* p = (const uint4*)(kpm + (size_t)b * SEQC + kt * 64) + tid;
        uint4 u = *p;
        v |= u.x | u.y | u.z | u.w;
    }
    #pragma unroll
    for (int off = 16; off >= 1; off >>= 1)
        v |= __shfl_xor_sync(0xffffffffu, v, off);
    __shared__ unsigned wv[8];
    if ((tid & 31) == 0) wv[tid >> 5] = v;
    __syncthreads();
    if (tid == 0) {
        unsigned r = 0;
        #pragma unroll
        for (int w = 0; w < 8; ++w) r |= wv[w];
        flags[(b * 32 + qt) * 32 + kt] = r ? 1 : 0;
    }
}

// ---------------- Y = X @ W^T + b : 128x128 tile, 8x8 register blocking ----------------
__global__ void __launch_bounds__(256, 2)
gemm_bias_kernel(const float* __restrict__ X, const float* __restrict__ W,
                 const float* __restrict__ bias, float* __restrict__ Y,
                 int M, int N, int K, int split_heads)
{
    __shared__ __align__(16) float sX[16][128];
    __shared__ __align__(16) float sW[16][128];
    const int tid = threadIdx.x;
    const int tn = tid & 15, tm = tid >> 4;
    const int n0 = blockIdx.x * 128, m0 = blockIdx.y * 128;
    const int lr = tid >> 1, lk = (tid & 1) << 3;

    const float* xg = X + (size_t)(m0 + lr) * K + lk;
    const float* wg = W + (size_t)(n0 + lr) * K + lk;

    float acc[8][8] = {};
    float4 xa0 = *(const float4*)(xg);
    float4 xa1 = *(const float4*)(xg + 4);
    float4 wa0 = *(const float4*)(wg);
    float4 wa1 = *(const float4*)(wg + 4);

    for (int k0 = 0; k0 < K; k0 += 16) {
        __syncthreads();
        sX[lk + 0][lr] = xa0.x; sX[lk + 1][lr] = xa0.y; sX[lk + 2][lr] = xa0.z; sX[lk + 3][lr] = xa0.w;
        sX[lk + 4][lr] = xa1.x; sX[lk + 5][lr] = xa1.y; sX[lk + 6][lr] = xa1.z; sX[lk + 7][lr] = xa1.w;
        sW[lk + 0][lr] = wa0.x; sW[lk + 1][lr] = wa0.y; sW[lk + 2][lr] = wa0.z; sW[lk + 3][lr] = wa0.w;
        sW[lk + 4][lr] = wa1.x; sW[lk + 5][lr] = wa1.y; sW[lk + 6][lr] = wa1.z; sW[lk + 7][lr] = wa1.w;
        __syncthreads();
        if (k0 + 16 < K) {
            xa0 = *(const float4*)(xg + k0 + 16);
            xa1 = *(const float4*)(xg + k0 + 20);
            wa0 = *(const float4*)(wg + k0 + 16);
            wa1 = *(const float4*)(wg + k0 + 20);
        }
        #pragma unroll
        for (int kk = 0; kk < 16; ++kk) {
            float4 a0 = *(const float4*)&sX[kk][tm * 4];
            float4 a1 = *(const float4*)&sX[kk][64 + tm * 4];
            float4 b0 = *(const float4*)&sW[kk][tn * 4];
            float4 b1 = *(const float4*)&sW[kk][64 + tn * 4];
            float av[8] = {a0.x, a0.y, a0.z, a0.w, a1.x, a1.y, a1.z, a1.w};
            float bv[8] = {b0.x, b0.y, b0.z, b0.w, b1.x, b1.y, b1.z, b1.w};
            #pragma unroll
            for (int i = 0; i < 8; ++i)
                #pragma unroll
                for (int j = 0; j < 8; ++j)
                    acc[i][j] = fmaf(av[i], bv[j], acc[i][j]);
        }
    }

    float4 bb0 = *(const float4*)&bias[n0 + tn * 4];
    float4 bb1 = *(const float4*)&bias[n0 + 64 + tn * 4];
    float bb[8] = {bb0.x, bb0.y, bb0.z, bb0.w, bb1.x, bb1.y, bb1.z, bb1.w};

    #pragma unroll
    for (int i = 0; i < 8; ++i) {
        int row = (i < 4) ? (tm * 4 + i) : (64 + tm * 4 + i - 4);
        int m = m0 + row;
        #pragma unroll
        for (int g = 0; g < 2; ++g) {
            float4 o;
            o.x = acc[i][g * 4 + 0] + bb[g * 4 + 0];
            o.y = acc[i][g * 4 + 1] + bb[g * 4 + 1];
            o.z = acc[i][g * 4 + 2] + bb[g * 4 + 2];
            o.w = acc[i][g * 4 + 3] + bb[g * 4 + 3];
            int c0 = n0 + g * 64 + tn * 4;
            if (split_heads) {
                int b = m >> 11, s = m & 2047;
                int h = c0 >> 6;
                int dk = c0 & 63;
                *(float4*)&Y[(((size_t)(b * NHEADC + h) * SEQC) + s) * DKC + dk] = o;
            } else {
                *(float4*)&Y[(size_t)m * N + c0] = o;
            }
        }
    }
}

// ---------------- flash attention: BQ=128, BK=64, 128 threads, 8x8 ----------------
#define SQT(d, r) sQt[(d) * 128 + (r)]
#define SKK(d, j) sK[(d) * 64 + (j)]
#define SVV(j, d) sV[(j) * 64 + (d)]
#define SPP(q, k) sP[(q) * 64 + (k)]

__global__ void __launch_bounds__(128)
attn_kernel(const float* __restrict__ Q, const float* __restrict__ Kp,
            const float* __restrict__ Vp,
            const unsigned char* __restrict__ am,
            const unsigned char* __restrict__ kpm,
            const int* __restrict__ flags,
            float* __restrict__ ctx)
{
    extern __shared__ __align__(16) float smemf[];
    float* sQt = smemf;                 // [64][128]  (d, q) pre-scaled
    float* sK  = smemf + 64 * 128;      // [64][64]   (d, j)
    float* sV  = sK + 64 * 64;          // [64][64]   (j, d)
    float* sP  = sV + 64 * 64;          // [128][64]  (q, k)

    const int qt = blockIdx.x;          // 0..15 (128-row q tiles)
    const int bh = blockIdx.y;          // 0..31
    const int b  = bh >> 4;
    const int h  = bh & 15;
    const int tid = threadIdx.x;
    const int tm = tid >> 3;            // 0..15 : q group of 8
    const int tn = tid & 7;             // 0..7  : k/d group of 8

    const float* Qb = Q  + ((size_t)bh * SEQC + qt * 128) * DKC;
    const float* Kb = Kp + (size_t)bh * SEQC * DKC;
    const float* Vb = Vp + (size_t)bh * SEQC * DKC;

    // load Q tile transposed, fold in 1/sqrt(dk)=0.125
    {
        int r = tid;  // 0..127
        const float4* src = (const float4*)(Qb + (size_t)r * DKC);
        #pragma unroll
        for (int u = 0; u < 16; ++u) {
            float4 v4 = src[u];
            int d0 = u * 4;
            SQT(d0 + 0, r) = v4.x * 0.125f;
            SQT(d0 + 1, r) = v4.y * 0.125f;
            SQT(d0 + 2, r) = v4.z * 0.125f;
            SQT(d0 + 3, r) = v4.w * 0.125f;
        }
    }

    float oacc[8][8] = {};
    float mrow[8], lrow[8];
    #pragma unroll
    for (int i = 0; i < 8; ++i) { mrow[i] = -1e30f; lrow[i] = 0.f; }

    for (int kt = 0; kt < SEQC / 64; ++kt) {
        __syncthreads();  // (A) prev PV reads of sV/sP complete
        {
            int j = tid >> 1, dq = (tid & 1) << 5;
            const float4* ks = (const float4*)(Kb + (size_t)(kt * 64 + j) * DKC + dq);
            const float4* vs = (const float4*)(Vb + (size_t)(kt * 64 + j) * DKC + dq);
            #pragma unroll
            for (int u = 0; u < 8; ++u) {
                float4 kv = ks[u];
                int d0 = dq + u * 4;
                SKK(d0 + 0, j) = kv.x; SKK(d0 + 1, j) = kv.y;
                SKK(d0 + 2, j) = kv.z; SKK(d0 + 3, j) = kv.w;
                float4 vv = vs[u];
                *(float4*)&SVV(j, d0) = vv;
            }
        }
        __syncthreads();  // (B) K/V ready

        // S = (Q/8) K^T : 8x8 per thread
        float s[8][8] = {};
        #pragma unroll 8
        for (int d = 0; d < DKC; ++d) {
            float4 a0 = *(const float4*)&SQT(d, tm * 8);
            float4 a1 = *(const float4*)&SQT(d, tm * 8 + 4);
            float4 b0 = *(const float4*)&SKK(d, tn * 8);
            float4 b1 = *(const float4*)&SKK(d, tn * 8 + 4);
            float av[8] = {a0.x, a0.y, a0.z, a0.w, a1.x, a1.y, a1.z, a1.w};
            float bv[8] = {b0.x, b0.y, b0.z, b0.w, b1.x, b1.y, b1.z, b1.w};
            #pragma unroll
            for (int i = 0; i < 8; ++i)
                #pragma unroll
                for (int j = 0; j < 8; ++j)
                    s[i][j] = fmaf(av[i], bv[j], s[i][j]);
        }

        // masks (slow path; flags are per 64x64 tile, q-tile here is 128)
        int fl = flags[(b * 32 + qt * 2) * 32 + kt] | flags[(b * 32 + qt * 2 + 1) * 32 + kt];
        if (fl) {
            #pragma unroll
            for (int i = 0; i < 8; ++i) {
                int qg = qt * 128 + tm * 8 + i;
                #pragma unroll
                for (int j = 0; j < 8; ++j) {
                    int kg = kt * 64 + tn * 8 + j;
                    if (am[((size_t)(b * SEQC + qg)) * SEQC + kg] | kpm[b * SEQC + kg])
                        s[i][j] = -1e30f;
                }
            }
        }

        // row max across the 8 lanes sharing tm (lanes are consecutive: xor 1,2,4)
        float tmax[8];
        #pragma unroll
        for (int i = 0; i < 8; ++i) {
            float v = s[i][0];
            #pragma unroll
            for (int j = 1; j < 8; ++j) v = fmaxf(v, s[i][j]);
            tmax[i] = v;
        }
        #pragma unroll
        for (int off = 4; off >= 1; off >>= 1)
            #pragma unroll
            for (int i = 0; i < 8; ++i)
                tmax[i] = fmaxf(tmax[i], __shfl_xor_sync(0xffffffffu, tmax[i], off));

        #pragma unroll
        for (int i = 0; i < 8; ++i) {
            float mn    = fmaxf(mrow[i], tmax[i]);
            float alpha = fast_exp(mrow[i] - mn);
            mrow[i] = mn;
            float ps = 0.f;
            #pragma unroll
            for (int j = 0; j < 8; ++j) {
                float p = fast_exp(s[i][j] - mn);
                if (s[i][j] <= -1e29f) p = 0.f;
                s[i][j] = p;
                ps += p;
            }
            #pragma unroll
            for (int off = 4; off >= 1; off >>= 1)
                ps += __shfl_xor_sync(0xffffffffu, ps, off);
            lrow[i] = fmaf(lrow[i], alpha, ps);
            #pragma unroll
            for (int j = 0; j < 8; ++j) oacc[i][j] *= alpha;
            // write P row chunk: contiguous 8 floats
            float4 p0 = {s[i][0], s[i][1], s[i][2], s[i][3]};
            float4 p1 = {s[i][4], s[i][5], s[i][6], s[i][7]};
            *(float4*)&SPP(tm * 8 + i, tn * 8)     = p0;
            *(float4*)&SPP(tm * 8 + i, tn * 8 + 4) = p1;
        }
        __syncthreads();  // (D) P visible

        // O += P V : 8 q-rows x 8 dims per thread
        #pragma unroll 4
        for (int k = 0; k < 64; ++k) {
            float4 v0 = *(const float4*)&SVV(k, tn * 8);
            float4 v1 = *(const float4*)&SVV(k, tn * 8 + 4);
            float vv[8] = {v0.x, v0.y, v0.z, v0.w, v1.x, v1.y, v1.z, v1.w};
            #pragma unroll
            for (int i = 0; i < 8; ++i) {
                float p = SPP(tm * 8 + i, k);
                #pragma unroll
                for (int j = 0; j < 8; ++j)
                    oacc[i][j] = fmaf(p, vv[j], oacc[i][j]);
            }
        }
    }

    // epilogue: normalize (fully-masked rows -> 0) and store
    #pragma unroll
    for (int i = 0; i < 8; ++i) {
        float r = (lrow[i] > 0.f) ? (1.0f / lrow[i]) : 0.f;
        size_t row = (size_t)b * SEQC + qt * 128 + tm * 8 + i;
        float4 o0 = {oacc[i][0] * r, oacc[i][1] * r, oacc[i][2] * r, oacc[i][3] * r};
        float4 o1 = {oacc[i][4] * r, oacc[i][5] * r, oacc[i][6] * r, oacc[i][7] * r};
        *(float4*)&ctx[row * D_MODELC + h * DKC + tn * 8]     = o0;
        *(float4*)&ctx[row * D_MODELC + h * DKC + tn * 8 + 4] = o1;
    }
}

// ---------------- launch ----------------
extern "C" void kernel_launch(void* const* d_in, const int* in_sizes, int n_in,
                              void* d_out, int out_size)
{
    const float* query = (const float*)d_in[0];
    const float* key   = (const float*)d_in[1];
    const float* value = (const float*)d_in[2];
    const unsigned char* am  = (const unsigned char*)d_in[3];
    const unsigned char* kpm = (const unsigned char*)d_in[4];
    const float* Wq = (const float*)d_in[5];
    const float* bq = (const float*)d_in[6];
    const float* Wk = (const float*)d_in[7];
    const float* bk = (const float*)d_in[8];
    const float* Wv = (const float*)d_in[9];
    const float* bv = (const float*)d_in[10];
    const float* Wo = (const float*)d_in[11];
    const float* bo = (const float*)d_in[12];
    float* out = (float*)d_out;

    float *Qp, *Kp, *Vp, *ctx; int* flags;
    cudaGetSymbolAddress((void**)&Qp,   g_Q);
    cudaGetSymbolAddress((void**)&Kp,   g_K);
    cudaGetSymbolAddress((void**)&Vp,   g_V);
    cudaGetSymbolAddress((void**)&ctx,  g_ctx);
    cudaGetSymbolAddress((void**)&flags, g_flags);

    static int smem_set = 0;
    const int attn_smem = (64 * 128 + 64 * 64 + 64 * 64 + 128 * 64) * 4;  // 96KB
    if (!smem_set) {
        cudaFuncSetAttribute(attn_kernel, cudaFuncAttributeMaxDynamicSharedMemorySize, attn_smem);
        smem_set = 1;
    }

    dim3 pg(32, 32, 2);
    prescan_kernel<<<pg, 256>>>(am, kpm, flags);

    dim3 gg(8, 32);  // N/128, M/128 with M=4096, N=1024
    gemm_bias_kernel<<<gg, 256>>>(query, Wq, bq, Qp, 4096, 1024, 1024, 1);
    gemm_bias_kernel<<<gg, 256>>>(key,   Wk, bk, Kp, 4096, 1024, 1024, 1);
    gemm_bias_kernel<<<gg, 256>>>(value, Wv, bv, Vp, 4096, 1024, 1024, 1);

    dim3 ag(16, 32);  // 128-row q tiles x (b*h)
    attn_kernel<<<ag, 128, attn_smem>>>(Qp, Kp, Vp, am, kpm, flags, ctx);

    gemm_bias_kernel<<<gg, 256>>>(ctx, Wo, bo, out, 4096, 1024, 1024, 0);
}

// round 9
// speedup vs baseline: 1.2967x; 1.1854x over previous
#include <cuda_runtime.h>
#include <cuda_bf16.h>
#include <cstdint>
#include <cstddef>

#define D_MODELC 1024
#define NHEADC   16
#define DKC      64
#define SEQC     2048
#define BATCHC   2
#define GKC      1024

// ---------------- device scratch (allocation-free) ----------------
__device__ float g_Q[BATCHC * NHEADC * SEQC * DKC];
__device__ float g_K[BATCHC * NHEADC * SEQC * DKC];
__device__ float g_V[BATCHC * NHEADC * SEQC * DKC];
__device__ float g_ctx[BATCHC * SEQC * D_MODELC];
__device__ int   g_flags[BATCHC * 32 * 32];

__device__ __nv_bfloat16 g_inhi[3 * 4096 * 1024];
__device__ __nv_bfloat16 g_inlo[3 * 4096 * 1024];
__device__ __nv_bfloat16 g_whi[4 * 1024 * 1024];
__device__ __nv_bfloat16 g_wlo[4 * 1024 * 1024];
__device__ __nv_bfloat16 g_chi[4096 * 1024];
__device__ __nv_bfloat16 g_clo[4096 * 1024];

// ---------------- helpers ----------------
__device__ __forceinline__ uint32_t smem_u32(const void* p) {
    uint32_t a;
    asm("{ .reg .u64 t; cvta.to.shared.u64 t, %1; cvt.u32.u64 %0, t; }" : "=r"(a) : "l"(p));
    return a;
}
#define LDSM_X4(R, addr) \
    asm volatile("ldmatrix.sync.aligned.m8n8.x4.shared.b16 {%0,%1,%2,%3}, [%4];" \
        : "=r"((R)[0]), "=r"((R)[1]), "=r"((R)[2]), "=r"((R)[3]) : "r"(addr))
#define MMA16816(C, A, B0, B1) \
    asm volatile("mma.sync.aligned.m16n8k16.row.col.f32.bf16.bf16.f32 " \
        "{%0,%1,%2,%3}, {%4,%5,%6,%7}, {%8,%9}, {%0,%1,%2,%3};" \
        : "+f"((C)[0]), "+f"((C)[1]), "+f"((C)[2]), "+f"((C)[3]) \
        : "r"((A)[0]), "r"((A)[1]), "r"((A)[2]), "r"((A)[3]), "r"(B0), "r"(B1))

// ---------------- fast exp (FMA pipe) ----------------
__device__ __forceinline__ float fast_exp(float x) {
    x = fmaxf(x, -87.0f);
    float t  = fmaf(x, 1.4426950408889634f, 12582912.0f);
    int   n  = __float_as_int(t) - 0x4B400000;
    float fn = t - 12582912.0f;
    float f  = fmaf(fn, -0.693359375f, x);
    f        = fmaf(fn,  2.12194899e-4f, f);
    float p  = 8.33333377e-3f;
    p = fmaf(p, f, 4.16666679e-2f);
    p = fmaf(p, f, 0.16666667f);
    p = fmaf(p, f, 0.5f);
    p = fmaf(p, f, 1.0f);
    p = fmaf(p, f, 1.0f);
    return __int_as_float(__float_as_int(p) + (n << 23));
}

// ---------------- fp32 -> bf16 hi/lo split ----------------
__global__ void __launch_bounds__(256)
cvt_kernel(const float* __restrict__ x, __nv_bfloat16* __restrict__ hi,
           __nv_bfloat16* __restrict__ lo, int n4)
{
    int i = blockIdx.x * blockDim.x + threadIdx.x;
    if (i >= n4) return;
    float4 v = ((const float4*)x)[i];
    __nv_bfloat16 h0 = __float2bfloat16(v.x);
    __nv_bfloat16 h1 = __float2bfloat16(v.y);
    __nv_bfloat16 h2 = __float2bfloat16(v.z);
    __nv_bfloat16 h3 = __float2bfloat16(v.w);
    __nv_bfloat16 l0 = __float2bfloat16(v.x - __bfloat162float(h0));
    __nv_bfloat16 l1 = __float2bfloat16(v.y - __bfloat162float(h1));
    __nv_bfloat16 l2 = __float2bfloat16(v.z - __bfloat162float(h2));
    __nv_bfloat16 l3 = __float2bfloat16(v.w - __bfloat162float(h3));
    __nv_bfloat162* H = (__nv_bfloat162*)hi;
    __nv_bfloat162* L = (__nv_bfloat162*)lo;
    H[i * 2]     = __nv_bfloat162(h0, h1);
    H[i * 2 + 1] = __nv_bfloat162(h2, h3);
    L[i * 2]     = __nv_bfloat162(l0, l1);
    L[i * 2 + 1] = __nv_bfloat162(l2, l3);
}

// ---------------- mask prescan ----------------
__global__ void __launch_bounds__(256)
prescan_kernel(const unsigned char* __restrict__ am,
               const unsigned char* __restrict__ kpm,
               int* __restrict__ flags)
{
    const int kt = blockIdx.x, qt = blockIdx.y, b = blockIdx.z;
    const int tid = threadIdx.x;
    unsigned v = 0;
    {
        int q = qt * 64 + (tid >> 2);
        const uint4* p = (const uint4*)(am + ((size_t)(b * SEQC + q)) * SEQC + kt * 64) + (tid & 3);
        uint4 u = *p;
        v = u.x | u.y | u.z | u.w;
    }
    if (tid < 4) {
        const uint4* p = (const uint4*)(kpm + (size_t)b * SEQC + kt * 64) + tid;
        uint4 u = *p;
        v |= u.x | u.y | u.z | u.w;
    }
    #pragma unroll
    for (int off = 16; off >= 1; off >>= 1)
        v |= __shfl_xor_sync(0xffffffffu, v, off);
    __shared__ unsigned wv[8];
    if ((tid & 31) == 0) wv[tid >> 5] = v;
    __syncthreads();
    if (tid == 0) {
        unsigned r = 0;
        #pragma unroll
        for (int w = 0; w < 8; ++w) r |= wv[w];
        flags[(b * 32 + qt) * 32 + kt] = r ? 1 : 0;
    }
}

// ---------------- tensor-core GEMM: Y[M,N] = A @ B^T + bias, bf16 2-way split ----------------
// mma.sync m16n8k16. CTA tile 128x128, BK=64. B is [N][K] row-major = col-major kxn,
// so B fragments load with NON-trans ldmatrix.
#define TSTR 72
#define TCG_SMEM_BYTES (4 * 128 * TSTR * 2)
__global__ void __launch_bounds__(256)
tc_gemm_kernel(const __nv_bfloat16* __restrict__ Ahi, const __nv_bfloat16* __restrict__ Alo,
               const __nv_bfloat16* __restrict__ Bhi, const __nv_bfloat16* __restrict__ Blo,
               const float* __restrict__ bias, float* __restrict__ Y,
               int N, int split_heads)
{
    extern __shared__ __align__(16) __nv_bfloat16 smem[];
    __nv_bfloat16* sAh = smem;
    __nv_bfloat16* sAl = sAh + 128 * TSTR;
    __nv_bfloat16* sBh = sAl + 128 * TSTR;
    __nv_bfloat16* sBl = sBh + 128 * TSTR;

    const int tid  = threadIdx.x;
    const int wid  = tid >> 5, lane = tid & 31;
    const int wm   = wid >> 2, wn = wid & 3;
    const int m0   = blockIdx.y * 128, n0 = blockIdx.x * 128;

    const int r = tid >> 1, hf = tid & 1;
    const size_t a_off = (size_t)(m0 + r) * GKC + hf * 32;
    const size_t b_off = (size_t)(n0 + r) * GKC + hf * 32;
    __nv_bfloat16* stA_h = sAh + r * TSTR + hf * 32;
    __nv_bfloat16* stA_l = sAl + r * TSTR + hf * 32;
    __nv_bfloat16* stB_h = sBh + r * TSTR + hf * 32;
    __nv_bfloat16* stB_l = sBl + r * TSTR + hf * 32;

    // ldmatrix lane addressing
    const int a_row  = wm * 64 + (lane & 15);
    const int a_coff = (lane >> 4) << 3;
    const int b_row  = wn * 32 + (lane & 7) + ((lane >> 4) << 3);
    const int b_koff = ((lane >> 3) & 1) << 3;
    const uint32_t uAh = smem_u32(sAh), uAl = smem_u32(sAl);
    const uint32_t uBh = smem_u32(sBh), uBl = smem_u32(sBl);

    float acc[4][4][4] = {};

    for (int kt = 0; kt < GKC / 64; ++kt) {
        const int k0 = kt * 64;
        __syncthreads();
        #pragma unroll
        for (int c = 0; c < 4; ++c) {
            *(uint4*)(stA_h + c * 8) = *(const uint4*)(Ahi + a_off + k0 + c * 8);
            *(uint4*)(stA_l + c * 8) = *(const uint4*)(Alo + a_off + k0 + c * 8);
            *(uint4*)(stB_h + c * 8) = *(const uint4*)(Bhi + b_off + k0 + c * 8);
            *(uint4*)(stB_l + c * 8) = *(const uint4*)(Blo + b_off + k0 + c * 8);
        }
        __syncthreads();

        #pragma unroll
        for (int ks = 0; ks < 4; ++ks) {
            const int kc = ks * 16;
            uint32_t Af[4][4], Bh2[2][4], Bl2[2][4];
            #pragma unroll
            for (int mt = 0; mt < 4; ++mt)
                LDSM_X4(Af[mt], uAh + ((a_row + mt * 16) * TSTR + kc + a_coff) * 2);
            #pragma unroll
            for (int nt2 = 0; nt2 < 2; ++nt2) {
                LDSM_X4(Bh2[nt2], uBh + ((b_row + nt2 * 16) * TSTR + kc + b_koff) * 2);
                LDSM_X4(Bl2[nt2], uBl + ((b_row + nt2 * 16) * TSTR + kc + b_koff) * 2);
            }
            // hi * hi
            #pragma unroll
            for (int mt = 0; mt < 4; ++mt)
                #pragma unroll
                for (int nt = 0; nt < 4; ++nt)
                    MMA16816(acc[mt][nt], Af[mt], Bh2[nt >> 1][(nt & 1) * 2], Bh2[nt >> 1][(nt & 1) * 2 + 1]);
            // hi * lo
            #pragma unroll
            for (int mt = 0; mt < 4; ++mt)
                #pragma unroll
                for (int nt = 0; nt < 4; ++nt)
                    MMA16816(acc[mt][nt], Af[mt], Bl2[nt >> 1][(nt & 1) * 2], Bl2[nt >> 1][(nt & 1) * 2 + 1]);
            // lo * hi (reuse A regs)
            #pragma unroll
            for (int mt = 0; mt < 4; ++mt)
                LDSM_X4(Af[mt], uAl + ((a_row + mt * 16) * TSTR + kc + a_coff) * 2);
            #pragma unroll
            for (int mt = 0; mt < 4; ++mt)
                #pragma unroll
                for (int nt = 0; nt < 4; ++nt)
                    MMA16816(acc[mt][nt], Af[mt], Bh2[nt >> 1][(nt & 1) * 2], Bh2[nt >> 1][(nt & 1) * 2 + 1]);
        }
    }

    const int er = lane >> 2, ec = (lane & 3) * 2;
    #pragma unroll
    for (int mt = 0; mt < 4; ++mt) {
        #pragma unroll
        for (int nt = 0; nt < 4; ++nt) {
            int col  = n0 + wn * 32 + nt * 8 + ec;
            float b0 = __ldg(&bias[col]), b1 = __ldg(&bias[col + 1]);
            #pragma unroll
            for (int half = 0; half < 2; ++half) {
                int m = m0 + wm * 64 + mt * 16 + er + half * 8;
                float2 o = {acc[mt][nt][half * 2] + b0, acc[mt][nt][half * 2 + 1] + b1};
                if (split_heads) {
                    int bb = m >> 11, s = m & 2047;
                    int hh = col >> 6, dk = col & 63;
                    *(float2*)&Y[(((size_t)(bb * NHEADC + hh) * SEQC) + s) * DKC + dk] = o;
                } else {
                    *(float2*)&Y[(size_t)m * N + col] = o;
                }
            }
        }
    }
}

// ---------------- flash attention: BQ=128, BK=64, 128 threads, 8x8 ----------------
#define PSTRIDE 68
#define SQT(d, r) sQt[(d) * 128 + (r)]
#define SKK(d, j) sK[(d) * 64 + (j)]
#define SVV(j, d) sV[(j) * 64 + (d)]

__global__ void __launch_bounds__(128)
attn_kernel(const float* __restrict__ Q, const float* __restrict__ Kp,
            const float* __restrict__ Vp,
            const unsigned char* __restrict__ am,
            const unsigned char* __restrict__ kpm,
            const int* __restrict__ flags,
            float* __restrict__ ctx)
{
    extern __shared__ __align__(16) float smemf[];
    float* sQt = smemf;
    float* sK  = smemf + 64 * 128;
    float* sV  = sK + 64 * 64;
    float* sP  = sV + 64 * 64;

    const int qt = blockIdx.x;
    const int bh = blockIdx.y;
    const int b  = bh >> 4;
    const int h  = bh & 15;
    const int tid = threadIdx.x;
    const int tm = tid >> 3;
    const int tn = tid & 7;

    const float* Qb = Q  + ((size_t)bh * SEQC + qt * 128) * DKC;
    const float* Kb = Kp + (size_t)bh * SEQC * DKC;
    const float* Vb = Vp + (size_t)bh * SEQC * DKC;

    {
        int r = tid;
        const float4* src = (const float4*)(Qb + (size_t)r * DKC);
        #pragma unroll
        for (int u = 0; u < 16; ++u) {
            float4 v4 = src[u];
            int d0 = u * 4;
            SQT(d0 + 0, r) = v4.x * 0.125f;
            SQT(d0 + 1, r) = v4.y * 0.125f;
            SQT(d0 + 2, r) = v4.z * 0.125f;
            SQT(d0 + 3, r) = v4.w * 0.125f;
        }
    }

    float oacc[8][8] = {};
    float mrow[8], lrow[8];
    #pragma unroll
    for (int i = 0; i < 8; ++i) { mrow[i] = -1e30f; lrow[i] = 0.f; }

    for (int kt = 0; kt < SEQC / 64; ++kt) {
        __syncthreads();
        {
            int j = tid >> 1, dq = (tid & 1) << 5;
            const float4* ks = (const float4*)(Kb + (size_t)(kt * 64 + j) * DKC + dq);
            const float4* vs = (const float4*)(Vb + (size_t)(kt * 64 + j) * DKC + dq);
            #pragma unroll
            for (int u = 0; u < 8; ++u) {
                float4 kv = ks[u];
                int d0 = dq + u * 4;
                SKK(d0 + 0, j) = kv.x; SKK(d0 + 1, j) = kv.y;
                SKK(d0 + 2, j) = kv.z; SKK(d0 + 3, j) = kv.w;
                float4 vv = vs[u];
                *(float4*)&SVV(j, d0) = vv;
            }
        }
        __syncthreads();

        float s[8][8] = {};
        #pragma unroll 8
        for (int d = 0; d < DKC; ++d) {
            float4 a0 = *(const float4*)&SQT(d, tm * 8);
            float4 a1 = *(const float4*)&SQT(d, tm * 8 + 4);
            float4 b0 = *(const float4*)&SKK(d, tn * 8);
            float4 b1 = *(const float4*)&SKK(d, tn * 8 + 4);
            float av[8] = {a0.x, a0.y, a0.z, a0.w, a1.x, a1.y, a1.z, a1.w};
            float bv[8] = {b0.x, b0.y, b0.z, b0.w, b1.x, b1.y, b1.z, b1.w};
            #pragma unroll
            for (int i = 0; i < 8; ++i)
                #pragma unroll
                for (int j = 0; j < 8; ++j)
                    s[i][j] = fmaf(av[i], bv[j], s[i][j]);
        }

        int fl = flags[(b * 32 + qt * 2) * 32 + kt] | flags[(b * 32 + qt * 2 + 1) * 32 + kt];
        if (fl) {
            #pragma unroll
            for (int i = 0; i < 8; ++i) {
                int qg = qt * 128 + tm * 8 + i;
                #pragma unroll
                for (int j = 0; j < 8; ++j) {
                    int kg = kt * 64 + tn * 8 + j;
                    if (am[((size_t)(b * SEQC + qg)) * SEQC + kg] | kpm[b * SEQC + kg])
                        s[i][j] = -1e30f;
                }
            }
        }

        float tmax[8];
        #pragma unroll
        for (int i = 0; i < 8; ++i) {
            float v = s[i][0];
            #pragma unroll
            for (int j = 1; j < 8; ++j) v = fmaxf(v, s[i][j]);
            tmax[i] = v;
        }
        #pragma unroll
        for (int off = 4; off >= 1; off >>= 1)
            #pragma unroll
            for (int i = 0; i < 8; ++i)
                tmax[i] = fmaxf(tmax[i], __shfl_xor_sync(0xffffffffu, tmax[i], off));

        #pragma unroll
        for (int i = 0; i < 8; ++i) {
            float mn    = fmaxf(mrow[i], tmax[i]);
            float alpha = fast_exp(mrow[i] - mn);
            mrow[i] = mn;
            float ps = 0.f;
            #pragma unroll
            for (int j = 0; j < 8; ++j) {
                float p = fast_exp(s[i][j] - mn);
                if (s[i][j] <= -1e29f) p = 0.f;
                s[i][j] = p;
                ps += p;
            }
            #pragma unroll
            for (int off = 4; off >= 1; off >>= 1)
                ps += __shfl_xor_sync(0xffffffffu, ps, off);
            lrow[i] = fmaf(lrow[i], alpha, ps);
            #pragma unroll
            for (int j = 0; j < 8; ++j) oacc[i][j] *= alpha;
            float4 p0 = {s[i][0], s[i][1], s[i][2], s[i][3]};
            float4 p1 = {s[i][4], s[i][5], s[i][6], s[i][7]};
            *(float4*)&sP[(tm * 8 + i) * PSTRIDE + tn * 8]     = p0;
            *(float4*)&sP[(tm * 8 + i) * PSTRIDE + tn * 8 + 4] = p1;
        }
        __syncthreads();

        #pragma unroll 4
        for (int k0 = 0; k0 < 64; k0 += 4) {
            float4 p4[8];
            #pragma unroll
            for (int i = 0; i < 8; ++i)
                p4[i] = *(const float4*)&sP[(tm * 8 + i) * PSTRIDE + k0];
            #pragma unroll
            for (int kk = 0; kk < 4; ++kk) {
                int k = k0 + kk;
                float4 v0 = *(const float4*)&SVV(k, tn * 8);
                float4 v1 = *(const float4*)&SVV(k, tn * 8 + 4);
                float vv[8] = {v0.x, v0.y, v0.z, v0.w, v1.x, v1.y, v1.z, v1.w};
                #pragma unroll
                for (int i = 0; i < 8; ++i) {
                    float p = (kk == 0) ? p4[i].x : (kk == 1) ? p4[i].y : (kk == 2) ? p4[i].z : p4[i].w;
                    #pragma unroll
                    for (int j = 0; j < 8; ++j)
                        oacc[i][j] = fmaf(p, vv[j], oacc[i][j]);
                }
            }
        }
    }

    #pragma unroll
    for (int i = 0; i < 8; ++i) {
        float r = (lrow[i] > 0.f) ? (1.0f / lrow[i]) : 0.f;
        size_t row = (size_t)b * SEQC + qt * 128 + tm * 8 + i;
        float4 o0 = {oacc[i][0] * r, oacc[i][1] * r, oacc[i][2] * r, oacc[i][3] * r};
        float4 o1 = {oacc[i][4] * r, oacc[i][5] * r, oacc[i][6] * r, oacc[i][7] * r};
        *(float4*)&ctx[row * D_MODELC + h * DKC + tn * 8]     = o0;
        *(float4*)&ctx[row * D_MODELC + h * DKC + tn * 8 + 4] = o1;
    }
}

// ---------------- launch ----------------
extern "C" void kernel_launch(void* const* d_in, const int* in_sizes, int n_in,
                              void* d_out, int out_size)
{
    const float* query = (const float*)d_in[0];
    const float* key   = (const float*)d_in[1];
    const float* value = (const float*)d_in[2];
    const unsigned char* am  = (const unsigned char*)d_in[3];
    const unsigned char* kpm = (const unsigned char*)d_in[4];
    const float* Wq = (const float*)d_in[5];
    const float* bq = (const float*)d_in[6];
    const float* Wk = (const float*)d_in[7];
    const float* bk = (const float*)d_in[8];
    const float* Wv = (const float*)d_in[9];
    const float* bv = (const float*)d_in[10];
    const float* Wo = (const float*)d_in[11];
    const float* bo = (const float*)d_in[12];
    float* out = (float*)d_out;

    float *Qp, *Kp, *Vp, *ctx; int* flags;
    __nv_bfloat16 *inhi, *inlo, *whi, *wlo, *chi, *clo;
    cudaGetSymbolAddress((void**)&Qp,    g_Q);
    cudaGetSymbolAddress((void**)&Kp,    g_K);
    cudaGetSymbolAddress((void**)&Vp,    g_V);
    cudaGetSymbolAddress((void**)&ctx,   g_ctx);
    cudaGetSymbolAddress((void**)&flags, g_flags);
    cudaGetSymbolAddress((void**)&inhi,  g_inhi);
    cudaGetSymbolAddress((void**)&inlo,  g_inlo);
    cudaGetSymbolAddress((void**)&whi,   g_whi);
    cudaGetSymbolAddress((void**)&wlo,   g_wlo);
    cudaGetSymbolAddress((void**)&chi,   g_chi);
    cudaGetSymbolAddress((void**)&clo,   g_clo);

    static int attr_set = 0;
    const int attn_smem = (64 * 128 + 64 * 64 + 64 * 64 + 128 * PSTRIDE) * 4;
    if (!attr_set) {
        cudaFuncSetAttribute(attn_kernel, cudaFuncAttributeMaxDynamicSharedMemorySize, attn_smem);
        cudaFuncSetAttribute(tc_gemm_kernel, cudaFuncAttributeMaxDynamicSharedMemorySize, TCG_SMEM_BYTES);
        attr_set = 1;
    }

    dim3 pg(32, 32, 2);
    prescan_kernel<<<pg, 256>>>(am, kpm, flags);

    const int IN_N = 4096 * 1024, W_N = 1024 * 1024;
    cvt_kernel<<<IN_N / 4 / 256, 256>>>(query, inhi,            inlo,            IN_N / 4);
    cvt_kernel<<<IN_N / 4 / 256, 256>>>(key,   inhi + IN_N,     inlo + IN_N,     IN_N / 4);
    cvt_kernel<<<IN_N / 4 / 256, 256>>>(value, inhi + 2 * IN_N, inlo + 2 * IN_N, IN_N / 4);
    cvt_kernel<<<W_N / 4 / 256, 256>>>(Wq, whi,           wlo,           W_N / 4);
    cvt_kernel<<<W_N / 4 / 256, 256>>>(Wk, whi + W_N,     wlo + W_N,     W_N / 4);
    cvt_kernel<<<W_N / 4 / 256, 256>>>(Wv, whi + 2 * W_N, wlo + 2 * W_N, W_N / 4);
    cvt_kernel<<<W_N / 4 / 256, 256>>>(Wo, whi + 3 * W_N, wlo + 3 * W_N, W_N / 4);

    dim3 gg(8, 32);  // N/128, M/128
    tc_gemm_kernel<<<gg, 256, TCG_SMEM_BYTES>>>(inhi,            inlo,            whi,           wlo,           bq, Qp, 1024, 1);
    tc_gemm_kernel<<<gg, 256, TCG_SMEM_BYTES>>>(inhi + IN_N,     inlo + IN_N,     whi + W_N,     wlo + W_N,     bk, Kp, 1024, 1);
    tc_gemm_kernel<<<gg, 256, TCG_SMEM_BYTES>>>(inhi + 2 * IN_N, inlo + 2 * IN_N, whi + 2 * W_N, wlo + 2 * W_N, bv, Vp, 1024, 1);

    dim3 ag(16, 32);
    attn_kernel<<<ag, 128, attn_smem>>>(Qp, Kp, Vp, am, kpm, flags, ctx);

    cvt_kernel<<<IN_N / 4 / 256, 256>>>(ctx, chi, clo, IN_N / 4);
    tc_gemm_kernel<<<gg, 256, TCG_SMEM_BYTES>>>(chi, clo, whi + 3 * W_N, wlo + 3 * W_N, bo, out, 1024, 0);
}

// round 10
// speedup vs baseline: 1.6307x; 1.2576x over previous
#include <cuda_runtime.h>
#include <cuda_bf16.h>
#include <cstdint>
#include <cstddef>

#define D_MODELC 1024
#define NHEADC   16
#define DKC      64
#define SEQC     2048
#define BATCHC   2
#define GKC      1024

// ---------------- device scratch (allocation-free) ----------------
__device__ int g_flags[BATCHC * 32 * 32];

__device__ __nv_bfloat16 g_inhi[3 * 4096 * 1024];
__device__ __nv_bfloat16 g_inlo[3 * 4096 * 1024];
__device__ __nv_bfloat16 g_whi[4 * 1024 * 1024];
__device__ __nv_bfloat16 g_wlo[4 * 1024 * 1024];
__device__ __nv_bfloat16 g_qhi[BATCHC * NHEADC * SEQC * DKC];
__device__ __nv_bfloat16 g_qlo[BATCHC * NHEADC * SEQC * DKC];
__device__ __nv_bfloat16 g_khi[BATCHC * NHEADC * SEQC * DKC];
__device__ __nv_bfloat16 g_klo[BATCHC * NHEADC * SEQC * DKC];
__device__ __nv_bfloat16 g_vhi[BATCHC * NHEADC * SEQC * DKC];
__device__ __nv_bfloat16 g_vlo[BATCHC * NHEADC * SEQC * DKC];
__device__ __nv_bfloat16 g_chi[4096 * 1024];
__device__ __nv_bfloat16 g_clo[4096 * 1024];

// ---------------- helpers ----------------
__device__ __forceinline__ uint32_t smem_u32(const void* p) {
    uint32_t a;
    asm("{ .reg .u64 t; cvta.to.shared.u64 t, %1; cvt.u32.u64 %0, t; }" : "=r"(a) : "l"(p));
    return a;
}
#define LDSM_X4(R, addr) \
    asm volatile("ldmatrix.sync.aligned.m8n8.x4.shared.b16 {%0,%1,%2,%3}, [%4];" \
        : "=r"((R)[0]), "=r"((R)[1]), "=r"((R)[2]), "=r"((R)[3]) : "r"(addr))
#define LDSM_X4_T(R, addr) \
    asm volatile("ldmatrix.sync.aligned.m8n8.x4.trans.shared.b16 {%0,%1,%2,%3}, [%4];" \
        : "=r"((R)[0]), "=r"((R)[1]), "=r"((R)[2]), "=r"((R)[3]) : "r"(addr))
#define MMA16816(C, A, B0, B1) \
    asm volatile("mma.sync.aligned.m16n8k16.row.col.f32.bf16.bf16.f32 " \
        "{%0,%1,%2,%3}, {%4,%5,%6,%7}, {%8,%9}, {%0,%1,%2,%3};" \
        : "+f"((C)[0]), "+f"((C)[1]), "+f"((C)[2]), "+f"((C)[3]) \
        : "r"((A)[0]), "r"((A)[1]), "r"((A)[2]), "r"((A)[3]), "r"(B0), "r"(B1))

__device__ __forceinline__ uint32_t pack2bf(float a, float b) {
    __nv_bfloat162 t = __floats2bfloat162_rn(a, b);
    return *(uint32_t*)&t;
}

// ---------------- fast exp (FMA pipe) ----------------
__device__ __forceinline__ float fast_exp(float x) {
    x = fmaxf(x, -87.0f);
    float t  = fmaf(x, 1.4426950408889634f, 12582912.0f);
    int   n  = __float_as_int(t) - 0x4B400000;
    float fn = t - 12582912.0f;
    float f  = fmaf(fn, -0.693359375f, x);
    f        = fmaf(fn,  2.12194899e-4f, f);
    float p  = 8.33333377e-3f;
    p = fmaf(p, f, 4.16666679e-2f);
    p = fmaf(p, f, 0.16666667f);
    p = fmaf(p, f, 0.5f);
    p = fmaf(p, f, 1.0f);
    p = fmaf(p, f, 1.0f);
    return __int_as_float(__float_as_int(p) + (n << 23));
}

// ---------------- fp32 -> bf16 hi/lo split ----------------
__global__ void __launch_bounds__(256)
cvt_kernel(const float* __restrict__ x, __nv_bfloat16* __restrict__ hi,
           __nv_bfloat16* __restrict__ lo, int n4)
{
    int i = blockIdx.x * blockDim.x + threadIdx.x;
    if (i >= n4) return;
    float4 v = ((const float4*)x)[i];
    __nv_bfloat16 h0 = __float2bfloat16(v.x);
    __nv_bfloat16 h1 = __float2bfloat16(v.y);
    __nv_bfloat16 h2 = __float2bfloat16(v.z);
    __nv_bfloat16 h3 = __float2bfloat16(v.w);
    __nv_bfloat16 l0 = __float2bfloat16(v.x - __bfloat162float(h0));
    __nv_bfloat16 l1 = __float2bfloat16(v.y - __bfloat162float(h1));
    __nv_bfloat16 l2 = __float2bfloat16(v.z - __bfloat162float(h2));
    __nv_bfloat16 l3 = __float2bfloat16(v.w - __bfloat162float(h3));
    __nv_bfloat162* H = (__nv_bfloat162*)hi;
    __nv_bfloat162* L = (__nv_bfloat162*)lo;
    H[i * 2]     = __nv_bfloat162(h0, h1);
    H[i * 2 + 1] = __nv_bfloat162(h2, h3);
    L[i * 2]     = __nv_bfloat162(l0, l1);
    L[i * 2 + 1] = __nv_bfloat162(l2, l3);
}

// ---------------- mask prescan ----------------
__global__ void __launch_bounds__(256)
prescan_kernel(const unsigned char* __restrict__ am,
               const unsigned char* __restrict__ kpm,
               int* __restrict__ flags)
{
    const int kt = blockIdx.x, qt = blockIdx.y, b = blockIdx.z;
    const int tid = threadIdx.x;
    unsigned v = 0;
    {
        int q = qt * 64 + (tid >> 2);
        const uint4* p = (const uint4*)(am + ((size_t)(b * SEQC + q)) * SEQC + kt * 64) + (tid & 3);
        uint4 u = *p;
        v = u.x | u.y | u.z | u.w;
    }
    if (tid < 4) {
        const uint4* p = (const uint4*)(kpm + (size_t)b * SEQC + kt * 64) + tid;
        uint4 u = *p;
        v |= u.x | u.y | u.z | u.w;
    }
    #pragma unroll
    for (int off = 16; off >= 1; off >>= 1)
        v |= __shfl_xor_sync(0xffffffffu, v, off);
    __shared__ unsigned wv[8];
    if ((tid & 31) == 0) wv[tid >> 5] = v;
    __syncthreads();
    if (tid == 0) {
        unsigned r = 0;
        #pragma unroll
        for (int w = 0; w < 8; ++w) r |= wv[w];
        flags[(b * 32 + qt) * 32 + kt] = r ? 1 : 0;
    }
}

// ---------------- tensor-core GEMM: Y = A @ B^T + bias, bf16 2-way split ----------------
// mode 0: fp32 output [m][N].  mode 2: bf16 hi/lo split output in [b,h,s,dk] head layout, scaled.
#define TSTR 72
#define TCG_SMEM_BYTES (4 * 128 * TSTR * 2)
__global__ void __launch_bounds__(256)
tc_gemm_kernel(const __nv_bfloat16* __restrict__ Ahi, const __nv_bfloat16* __restrict__ Alo,
               const __nv_bfloat16* __restrict__ Bhi, const __nv_bfloat16* __restrict__ Blo,
               const float* __restrict__ bias, float* __restrict__ Y,
               __nv_bfloat16* __restrict__ Yhi, __nv_bfloat16* __restrict__ Ylo,
               float scale, int N, int mode)
{
    extern __shared__ __align__(16) __nv_bfloat16 smem[];
    __nv_bfloat16* sAh = smem;
    __nv_bfloat16* sAl = sAh + 128 * TSTR;
    __nv_bfloat16* sBh = sAl + 128 * TSTR;
    __nv_bfloat16* sBl = sBh + 128 * TSTR;

    const int tid  = threadIdx.x;
    const int wid  = tid >> 5, lane = tid & 31;
    const int wm   = wid >> 2, wn = wid & 3;
    const int m0   = blockIdx.y * 128, n0 = blockIdx.x * 128;

    const int r = tid >> 1, hf = tid & 1;
    const size_t a_off = (size_t)(m0 + r) * GKC + hf * 32;
    const size_t b_off = (size_t)(n0 + r) * GKC + hf * 32;
    __nv_bfloat16* stA_h = sAh + r * TSTR + hf * 32;
    __nv_bfloat16* stA_l = sAl + r * TSTR + hf * 32;
    __nv_bfloat16* stB_h = sBh + r * TSTR + hf * 32;
    __nv_bfloat16* stB_l = sBl + r * TSTR + hf * 32;

    const int a_row  = wm * 64 + (lane & 15);
    const int a_coff = (lane >> 4) << 3;
    const int b_row  = wn * 32 + (lane & 7) + ((lane >> 4) << 3);
    const int b_koff = ((lane >> 3) & 1) << 3;
    const uint32_t uAh = smem_u32(sAh), uAl = smem_u32(sAl);
    const uint32_t uBh = smem_u32(sBh), uBl = smem_u32(sBl);

    float acc[4][4][4] = {};

    for (int kt = 0; kt < GKC / 64; ++kt) {
        const int k0 = kt * 64;
        __syncthreads();
        #pragma unroll
        for (int c = 0; c < 4; ++c) {
            *(uint4*)(stA_h + c * 8) = *(const uint4*)(Ahi + a_off + k0 + c * 8);
            *(uint4*)(stA_l + c * 8) = *(const uint4*)(Alo + a_off + k0 + c * 8);
            *(uint4*)(stB_h + c * 8) = *(const uint4*)(Bhi + b_off + k0 + c * 8);
            *(uint4*)(stB_l + c * 8) = *(const uint4*)(Blo + b_off + k0 + c * 8);
        }
        __syncthreads();

        #pragma unroll
        for (int ks = 0; ks < 4; ++ks) {
            const int kc = ks * 16;
            uint32_t Af[4][4], Bh2[2][4], Bl2[2][4];
            #pragma unroll
            for (int mt = 0; mt < 4; ++mt)
                LDSM_X4(Af[mt], uAh + ((a_row + mt * 16) * TSTR + kc + a_coff) * 2);
            #pragma unroll
            for (int nt2 = 0; nt2 < 2; ++nt2) {
                LDSM_X4(Bh2[nt2], uBh + ((b_row + nt2 * 16) * TSTR + kc + b_koff) * 2);
                LDSM_X4(Bl2[nt2], uBl + ((b_row + nt2 * 16) * TSTR + kc + b_koff) * 2);
            }
            #pragma unroll
            for (int mt = 0; mt < 4; ++mt)
                #pragma unroll
                for (int nt = 0; nt < 4; ++nt)
                    MMA16816(acc[mt][nt], Af[mt], Bh2[nt >> 1][(nt & 1) * 2], Bh2[nt >> 1][(nt & 1) * 2 + 1]);
            #pragma unroll
            for (int mt = 0; mt < 4; ++mt)
                #pragma unroll
                for (int nt = 0; nt < 4; ++nt)
                    MMA16816(acc[mt][nt], Af[mt], Bl2[nt >> 1][(nt & 1) * 2], Bl2[nt >> 1][(nt & 1) * 2 + 1]);
            #pragma unroll
            for (int mt = 0; mt < 4; ++mt)
                LDSM_X4(Af[mt], uAl + ((a_row + mt * 16) * TSTR + kc + a_coff) * 2);
            #pragma unroll
            for (int mt = 0; mt < 4; ++mt)
                #pragma unroll
                for (int nt = 0; nt < 4; ++nt)
                    MMA16816(acc[mt][nt], Af[mt], Bh2[nt >> 1][(nt & 1) * 2], Bh2[nt >> 1][(nt & 1) * 2 + 1]);
        }
    }

    const int er = lane >> 2, ec = (lane & 3) * 2;
    #pragma unroll
    for (int mt = 0; mt < 4; ++mt) {
        #pragma unroll
        for (int nt = 0; nt < 4; ++nt) {
            int col  = n0 + wn * 32 + nt * 8 + ec;
            float b0 = __ldg(&bias[col]), b1 = __ldg(&bias[col + 1]);
            #pragma unroll
            for (int half = 0; half < 2; ++half) {
                int m = m0 + wm * 64 + mt * 16 + er + half * 8;
                float vx = (acc[mt][nt][half * 2]     + b0) * scale;
                float vy = (acc[mt][nt][half * 2 + 1] + b1) * scale;
                if (mode == 2) {
                    int bb = m >> 11, s = m & 2047;
                    int hh = col >> 6, dk = col & 63;
                    size_t idx = (((size_t)(bb * NHEADC + hh) * SEQC) + s) * DKC + dk;
                    __nv_bfloat16 hx = __float2bfloat16(vx), hy = __float2bfloat16(vy);
                    *(__nv_bfloat162*)&Yhi[idx] = __nv_bfloat162(hx, hy);
                    *(__nv_bfloat162*)&Ylo[idx] = __nv_bfloat162(
                        __float2bfloat16(vx - __bfloat162float(hx)),
                        __float2bfloat16(vy - __bfloat162float(hy)));
                } else {
                    *(float2*)&Y[(size_t)m * N + col] = make_float2(vx, vy);
                }
            }
        }
    }
}

// ---------------- flash attention on mma.sync: BQ=128, BK=64, 8 warps ----------------
// Each warp owns 16 q-rows and all 64 keys of the tile. P stays in registers.
#define ASTR 72
__global__ void __launch_bounds__(256)
attn_kernel(const __nv_bfloat16* __restrict__ Qhi, const __nv_bfloat16* __restrict__ Qlo,
            const __nv_bfloat16* __restrict__ Khi, const __nv_bfloat16* __restrict__ Klo,
            const __nv_bfloat16* __restrict__ Vhi, const __nv_bfloat16* __restrict__ Vlo,
            const unsigned char* __restrict__ am,
            const unsigned char* __restrict__ kpm,
            const int* __restrict__ flags,
            __nv_bfloat16* __restrict__ ctxhi, __nv_bfloat16* __restrict__ ctxlo)
{
    extern __shared__ __align__(16) __nv_bfloat16 smem[];
    // Q staging (overwritten later): sQh [128][ASTR], sQl
    __nv_bfloat16* sQh = smem;
    __nv_bfloat16* sQl = smem + 128 * ASTR;
    // K/V tiles: sKh [64][ASTR], sKl, sVh, sVl
    __nv_bfloat16* sKh = smem;
    __nv_bfloat16* sKl = smem + 64 * ASTR;
    __nv_bfloat16* sVh = smem + 2 * 64 * ASTR;
    __nv_bfloat16* sVl = smem + 3 * 64 * ASTR;

    const int qt = blockIdx.x;       // 0..15
    const int bh = blockIdx.y;       // 0..31
    const int b  = bh >> 4;
    const int h  = bh & 15;
    const int tid = threadIdx.x;
    const int wid = tid >> 5, lane = tid & 31;
    const int er = lane >> 2, ec = (lane & 3) * 2;

    const size_t qbase = ((size_t)bh * SEQC + qt * 128) * DKC;
    const size_t kvbase = (size_t)bh * SEQC * DKC;

    // ---- stage Q tile (128x64 hi/lo) into smem, then pull A-fragments ----
    {
        int r = tid >> 1, hf = tid & 1;
        #pragma unroll
        for (int u = 0; u < 4; ++u) {
            int c = hf * 4 + u;   // uint4 chunk 0..7
            *(uint4*)(sQh + r * ASTR + c * 8) = *(const uint4*)(Qhi + qbase + (size_t)r * DKC + c * 8);
            *(uint4*)(sQl + r * ASTR + c * 8) = *(const uint4*)(Qlo + qbase + (size_t)r * DKC + c * 8);
        }
    }
    __syncthreads();

    uint32_t Qh[4][4], Ql[4][4];
    {
        const uint32_t uQh = smem_u32(sQh), uQl = smem_u32(sQl);
        const int a_row  = wid * 16 + (lane & 15);
        const int a_coff = (lane >> 4) << 3;
        #pragma unroll
        for (int ks = 0; ks < 4; ++ks) {
            LDSM_X4(Qh[ks], uQh + (a_row * ASTR + ks * 16 + a_coff) * 2);
            LDSM_X4(Ql[ks], uQl + (a_row * ASTR + ks * 16 + a_coff) * 2);
        }
    }
    __syncthreads();  // Q fragments extracted; smem now free for K/V

    // ldmatrix addressing for K (B operand, [n][k] non-trans) and V ([k][n] trans)
    const int b_row  = (lane & 7) + ((lane >> 4) << 3);
    const int b_koff = ((lane >> 3) & 1) << 3;
    const int v_row  = (lane & 7) + (((lane >> 3) & 1) << 3);
    const int v_noff = (lane >> 4) << 3;
    const uint32_t uKh = smem_u32(sKh), uKl = smem_u32(sKl);
    const uint32_t uVh = smem_u32(sVh), uVl = smem_u32(sVl);

    float oacc[8][4] = {};
    float m0r = -1e30f, m1r = -1e30f, l0r = 0.f, l1r = 0.f;

    for (int kt = 0; kt < SEQC / 64; ++kt) {
        __syncthreads();   // previous iteration's reads done
        {
            int r = tid >> 2, qc = tid & 3;
            const size_t g = kvbase + (size_t)(kt * 64 + r) * DKC;
            #pragma unroll
            for (int u = 0; u < 2; ++u) {
                int c = qc * 2 + u;  // uint4 chunk 0..7
                *(uint4*)(sKh + r * ASTR + c * 8) = *(const uint4*)(Khi + g + c * 8);
                *(uint4*)(sKl + r * ASTR + c * 8) = *(const uint4*)(Klo + g + c * 8);
                *(uint4*)(sVh + r * ASTR + c * 8) = *(const uint4*)(Vhi + g + c * 8);
                *(uint4*)(sVl + r * ASTR + c * 8) = *(const uint4*)(Vlo + g + c * 8);
            }
        }
        __syncthreads();

        // ---- S = (Q/8) K^T : 8 n-tiles (64 keys), fp32 accum ----
        float s[8][4] = {};
        #pragma unroll
        for (int ks = 0; ks < 4; ++ks) {
            const int kc = ks * 16;
            uint32_t KB[4][4];
            #pragma unroll
            for (int g = 0; g < 4; ++g)
                LDSM_X4(KB[g], uKh + ((g * 16 + b_row) * ASTR + kc + b_koff) * 2);
            #pragma unroll
            for (int nt = 0; nt < 8; ++nt)
                MMA16816(s[nt], Qh[ks], KB[nt >> 1][(nt & 1) * 2], KB[nt >> 1][(nt & 1) * 2 + 1]);
            #pragma unroll
            for (int nt = 0; nt < 8; ++nt)
                MMA16816(s[nt], Ql[ks], KB[nt >> 1][(nt & 1) * 2], KB[nt >> 1][(nt & 1) * 2 + 1]);
            #pragma unroll
            for (int g = 0; g < 4; ++g)
                LDSM_X4(KB[g], uKl + ((g * 16 + b_row) * ASTR + kc + b_koff) * 2);
            #pragma unroll
            for (int nt = 0; nt < 8; ++nt)
                MMA16816(s[nt], Qh[ks], KB[nt >> 1][(nt & 1) * 2], KB[nt >> 1][(nt & 1) * 2 + 1]);
        }

        // ---- masks (slow path) ----
        int fl = flags[(b * 32 + qt * 2) * 32 + kt] | flags[(b * 32 + qt * 2 + 1) * 32 + kt];
        if (fl) {
            int q0 = qt * 128 + wid * 16 + er;
            #pragma unroll
            for (int nt = 0; nt < 8; ++nt) {
                int kg = kt * 64 + nt * 8 + ec;
                #pragma unroll
                for (int c = 0; c < 4; ++c) {
                    int qg = q0 + (c >> 1) * 8;
                    int kk = kg + (c & 1);
                    if (am[((size_t)(b * SEQC + qg)) * SEQC + kk] | kpm[b * SEQC + kk])
                        s[nt][c] = -1e30f;
                }
            }
        }

        // ---- online softmax (rows er and er+8, reduce over 4-lane quad) ----
        float mx0 = -1e30f, mx1 = -1e30f;
        #pragma unroll
        for (int nt = 0; nt < 8; ++nt) {
            mx0 = fmaxf(mx0, fmaxf(s[nt][0], s[nt][1]));
            mx1 = fmaxf(mx1, fmaxf(s[nt][2], s[nt][3]));
        }
        mx0 = fmaxf(mx0, __shfl_xor_sync(0xffffffffu, mx0, 1));
        mx0 = fmaxf(mx0, __shfl_xor_sync(0xffffffffu, mx0, 2));
        mx1 = fmaxf(mx1, __shfl_xor_sync(0xffffffffu, mx1, 1));
        mx1 = fmaxf(mx1, __shfl_xor_sync(0xffffffffu, mx1, 2));

        float mn0 = fmaxf(m0r, mx0), mn1 = fmaxf(m1r, mx1);
        float al0 = fast_exp(m0r - mn0), al1 = fast_exp(m1r - mn1);
        m0r = mn0; m1r = mn1;

        float sum0 = 0.f, sum1 = 0.f;
        #pragma unroll
        for (int nt = 0; nt < 8; ++nt) {
            float p0 = fast_exp(s[nt][0] - mn0); if (s[nt][0] <= -1e29f) p0 = 0.f;
            float p1 = fast_exp(s[nt][1] - mn0); if (s[nt][1] <= -1e29f) p1 = 0.f;
            float p2 = fast_exp(s[nt][2] - mn1); if (s[nt][2] <= -1e29f) p2 = 0.f;
            float p3 = fast_exp(s[nt][3] - mn1); if (s[nt][3] <= -1e29f) p3 = 0.f;
            s[nt][0] = p0; s[nt][1] = p1; s[nt][2] = p2; s[nt][3] = p3;
            sum0 += p0 + p1; sum1 += p2 + p3;
        }
        sum0 += __shfl_xor_sync(0xffffffffu, sum0, 1);
        sum0 += __shfl_xor_sync(0xffffffffu, sum0, 2);
        sum1 += __shfl_xor_sync(0xffffffffu, sum1, 1);
        sum1 += __shfl_xor_sync(0xffffffffu, sum1, 2);
        l0r = fmaf(l0r, al0, sum0);
        l1r = fmaf(l1r, al1, sum1);
        #pragma unroll
        for (int nt = 0; nt < 8; ++nt) {
            oacc[nt][0] *= al0; oacc[nt][1] *= al0;
            oacc[nt][2] *= al1; oacc[nt][3] *= al1;
        }

        // ---- O += P V : P packed in registers (C-frag == A-frag layout) ----
        #pragma unroll
        for (int ks = 0; ks < 4; ++ks) {
            const int t0 = 2 * ks, t1 = 2 * ks + 1;
            uint32_t aPh[4], aPl[4];
            {
                float v00 = s[t0][0], v01 = s[t0][1], v02 = s[t0][2], v03 = s[t0][3];
                float v10 = s[t1][0], v11 = s[t1][1], v12 = s[t1][2], v13 = s[t1][3];
                __nv_bfloat16 h;
                float r00, r01, r02, r03, r10, r11, r12, r13;
                h = __float2bfloat16(v00); r00 = v00 - __bfloat162float(h);
                h = __float2bfloat16(v01); r01 = v01 - __bfloat162float(h);
                h = __float2bfloat16(v02); r02 = v02 - __bfloat162float(h);
                h = __float2bfloat16(v03); r03 = v03 - __bfloat162float(h);
                h = __float2bfloat16(v10); r10 = v10 - __bfloat162float(h);
                h = __float2bfloat16(v11); r11 = v11 - __bfloat162float(h);
                h = __float2bfloat16(v12); r12 = v12 - __bfloat162float(h);
                h = __float2bfloat16(v13); r13 = v13 - __bfloat162float(h);
                aPh[0] = pack2bf(v00, v01); aPh[1] = pack2bf(v02, v03);
                aPh[2] = pack2bf(v10, v11); aPh[3] = pack2bf(v12, v13);
                aPl[0] = pack2bf(r00, r01); aPl[1] = pack2bf(r02, r03);
                aPl[2] = pack2bf(r10, r11); aPl[3] = pack2bf(r12, r13);
            }
            uint32_t VB[4][4];
            #pragma unroll
            for (int g = 0; g < 4; ++g)
                LDSM_X4_T(VB[g], uVh + ((ks * 16 + v_row) * ASTR + g * 16 + v_noff) * 2);
            #pragma unroll
            for (int nt = 0; nt < 8; ++nt)
                MMA16816(oacc[nt], aPh, VB[nt >> 1][(nt & 1) * 2], VB[nt >> 1][(nt & 1) * 2 + 1]);
            #pragma unroll
            for (int nt = 0; nt < 8; ++nt)
                MMA16816(oacc[nt], aPl, VB[nt >> 1][(nt & 1) * 2], VB[nt >> 1][(nt & 1) * 2 + 1]);
            #pragma unroll
            for (int g = 0; g < 4; ++g)
                LDSM_X4_T(VB[g], uVl + ((ks * 16 + v_row) * ASTR + g * 16 + v_noff) * 2);
            #pragma unroll
            for (int nt = 0; nt < 8; ++nt)
                MMA16816(oacc[nt], aPh, VB[nt >> 1][(nt & 1) * 2], VB[nt >> 1][(nt & 1) * 2 + 1]);
        }
    }

    // ---- epilogue: normalize, write ctx as bf16 hi/lo split ----
    float r0 = (l0r > 0.f) ? (1.0f / l0r) : 0.f;
    float r1 = (l1r > 0.f) ? (1.0f / l1r) : 0.f;
    const int q0 = qt * 128 + wid * 16 + er;
    #pragma unroll
    for (int nt = 0; nt < 8; ++nt) {
        int col = h * DKC + nt * 8 + ec;
        {
            float vx = oacc[nt][0] * r0, vy = oacc[nt][1] * r0;
            size_t idx = ((size_t)(b * SEQC + q0)) * D_MODELC + col;
            __nv_bfloat16 hx = __float2bfloat16(vx), hy = __float2bfloat16(vy);
            *(__nv_bfloat162*)&ctxhi[idx] = __nv_bfloat162(hx, hy);
            *(__nv_bfloat162*)&ctxlo[idx] = __nv_bfloat162(
                __float2bfloat16(vx - __bfloat162float(hx)),
                __float2bfloat16(vy - __bfloat162float(hy)));
        }
        {
            float vx = oacc[nt][2] * r1, vy = oacc[nt][3] * r1;
            size_t idx = ((size_t)(b * SEQC + q0 + 8)) * D_MODELC + col;
            __nv_bfloat16 hx = __float2bfloat16(vx), hy = __float2bfloat16(vy);
            *(__nv_bfloat162*)&ctxhi[idx] = __nv_bfloat162(hx, hy);
            *(__nv_bfloat162*)&ctxlo[idx] = __nv_bfloat162(
                __float2bfloat16(vx - __bfloat162float(hx)),
                __float2bfloat16(vy - __bfloat162float(hy)));
        }
    }
}

// ---------------- launch ----------------
extern "C" void kernel_launch(void* const* d_in, const int* in_sizes, int n_in,
                              void* d_out, int out_size)
{
    const float* query = (const float*)d_in[0];
    const float* key   = (const float*)d_in[1];
    const float* value = (const float*)d_in[2];
    const unsigned char* am  = (const unsigned char*)d_in[3];
    const unsigned char* kpm = (const unsigned char*)d_in[4];
    const float* Wq = (const float*)d_in[5];
    const float* bq = (const float*)d_in[6];
    const float* Wk = (const float*)d_in[7];
    const float* bk = (const float*)d_in[8];
    const float* Wv = (const float*)d_in[9];
    const float* bv = (const float*)d_in[10];
    const float* Wo = (const float*)d_in[11];
    const float* bo = (const float*)d_in[12];
    float* out = (float*)d_out;

    int* flags;
    __nv_bfloat16 *inhi, *inlo, *whi, *wlo, *chi, *clo;
    __nv_bfloat16 *qhi, *qlo, *khi, *klo, *vhi, *vlo;
    cudaGetSymbolAddress((void**)&flags, g_flags);
    cudaGetSymbolAddress((void**)&inhi,  g_inhi);
    cudaGetSymbolAddress((void**)&inlo,  g_inlo);
    cudaGetSymbolAddress((void**)&whi,   g_whi);
    cudaGetSymbolAddress((void**)&wlo,   g_wlo);
    cudaGetSymbolAddress((void**)&chi,   g_chi);
    cudaGetSymbolAddress((void**)&clo,   g_clo);
    cudaGetSymbolAddress((void**)&qhi,   g_qhi);
    cudaGetSymbolAddress((void**)&qlo,   g_qlo);
    cudaGetSymbolAddress((void**)&khi,   g_khi);
    cudaGetSymbolAddress((void**)&klo,   g_klo);
    cudaGetSymbolAddress((void**)&vhi,   g_vhi);
    cudaGetSymbolAddress((void**)&vlo,   g_vlo);

    static int attr_set = 0;
    const int attn_smem = 2 * 128 * ASTR * 2;   // Q stage == K/V area (36864 B)
    if (!attr_set) {
        cudaFuncSetAttribute(attn_kernel, cudaFuncAttributeMaxDynamicSharedMemorySize, attn_smem);
        cudaFuncSetAttribute(tc_gemm_kernel, cudaFuncAttributeMaxDynamicSharedMemorySize, TCG_SMEM_BYTES);
        attr_set = 1;
    }

    dim3 pg(32, 32, 2);
    prescan_kernel<<<pg, 256>>>(am, kpm, flags);

    const int IN_N = 4096 * 1024, W_N = 1024 * 1024;
    cvt_kernel<<<IN_N / 4 / 256, 256>>>(query, inhi,            inlo,            IN_N / 4);
    cvt_kernel<<<IN_N / 4 / 256, 256>>>(key,   inhi + IN_N,     inlo + IN_N,     IN_N / 4);
    cvt_kernel<<<IN_N / 4 / 256, 256>>>(value, inhi + 2 * IN_N, inlo + 2 * IN_N, IN_N / 4);
    cvt_kernel<<<W_N / 4 / 256, 256>>>(Wq, whi,           wlo,           W_N / 4);
    cvt_kernel<<<W_N / 4 / 256, 256>>>(Wk, whi + W_N,     wlo + W_N,     W_N / 4);
    cvt_kernel<<<W_N / 4 / 256, 256>>>(Wv, whi + 2 * W_N, wlo + 2 * W_N, W_N / 4);
    cvt_kernel<<<W_N / 4 / 256, 256>>>(Wo, whi + 3 * W_N, wlo + 3 * W_N, W_N / 4);

    dim3 gg(8, 32);  // N/128, M/128
    tc_gemm_kernel<<<gg, 256, TCG_SMEM_BYTES>>>(inhi,            inlo,            whi,           wlo,           bq, nullptr, qhi, qlo, 0.125f, 1024, 2);
    tc_gemm_kernel<<<gg, 256, TCG_SMEM_BYTES>>>(inhi + IN_N,     inlo + IN_N,     whi + W_N,     wlo + W_N,     bk, nullptr, khi, klo, 1.0f,   1024, 2);
    tc_gemm_kernel<<<gg, 256, TCG_SMEM_BYTES>>>(inhi + 2 * IN_N, inlo + 2 * IN_N, whi + 2 * W_N, wlo + 2 * W_N, bv, nullptr, vhi, vlo, 1.0f,   1024, 2);

    dim3 ag(16, 32);
    attn_kernel<<<ag, 256, attn_smem>>>(qhi, qlo, khi, klo, vhi, vlo, am, kpm, flags, chi, clo);

    tc_gemm_kernel<<<gg, 256, TCG_SMEM_BYTES>>>(chi, clo, whi + 3 * W_N, wlo + 3 * W_N, bo, out, nullptr, nullptr, 1.0f, 1024, 0);
}

// round 12
// speedup vs baseline: 2.4679x; 1.5134x over previous
#include <cuda_runtime.h>
#include <cuda_bf16.h>
#include <cstdint>
#include <cstddef>

#define D_MODELC 1024
#define NHEADC   16
#define DKC      64
#define SEQC     2048
#define BATCHC   2
#define GKC      1024

// ---------------- device scratch (allocation-free) ----------------
__device__ int g_flags[BATCHC * 32 * 32];

__device__ __nv_bfloat16 g_inhi[3 * 4096 * 1024];
__device__ __nv_bfloat16 g_inlo[3 * 4096 * 1024];
__device__ __nv_bfloat16 g_whi[4 * 1024 * 1024];
__device__ __nv_bfloat16 g_wlo[4 * 1024 * 1024];
__device__ __nv_bfloat16 g_qhi[BATCHC * NHEADC * SEQC * DKC];
__device__ __nv_bfloat16 g_qlo[BATCHC * NHEADC * SEQC * DKC];
__device__ __nv_bfloat16 g_khi[BATCHC * NHEADC * SEQC * DKC];
__device__ __nv_bfloat16 g_klo[BATCHC * NHEADC * SEQC * DKC];
__device__ __nv_bfloat16 g_vhi[BATCHC * NHEADC * SEQC * DKC];
__device__ __nv_bfloat16 g_vlo[BATCHC * NHEADC * SEQC * DKC];
__device__ __nv_bfloat16 g_chi[4096 * 1024];
__device__ __nv_bfloat16 g_clo[4096 * 1024];

// ---------------- helpers ----------------
__device__ __forceinline__ uint32_t smem_u32(const void* p) {
    uint32_t a;
    asm("{ .reg .u64 t; cvta.to.shared.u64 t, %1; cvt.u32.u64 %0, t; }" : "=r"(a) : "l"(p));
    return a;
}
#define LDSM_X4(R, addr) \
    asm volatile("ldmatrix.sync.aligned.m8n8.x4.shared.b16 {%0,%1,%2,%3}, [%4];" \
        : "=r"((R)[0]), "=r"((R)[1]), "=r"((R)[2]), "=r"((R)[3]) : "r"(addr))
#define LDSM_X4_T(R, addr) \
    asm volatile("ldmatrix.sync.aligned.m8n8.x4.trans.shared.b16 {%0,%1,%2,%3}, [%4];" \
        : "=r"((R)[0]), "=r"((R)[1]), "=r"((R)[2]), "=r"((R)[3]) : "r"(addr))
#define MMA16816(C, A, B0, B1) \
    asm volatile("mma.sync.aligned.m16n8k16.row.col.f32.bf16.bf16.f32 " \
        "{%0,%1,%2,%3}, {%4,%5,%6,%7}, {%8,%9}, {%0,%1,%2,%3};" \
        : "+f"((C)[0]), "+f"((C)[1]), "+f"((C)[2]), "+f"((C)[3]) \
        : "r"((A)[0]), "r"((A)[1]), "r"((A)[2]), "r"((A)[3]), "r"(B0), "r"(B1))
#define CP_ASYNC16(saddr, gptr) \
    asm volatile("cp.async.cg.shared.global [%0], [%1], 16;" :: "r"(saddr), "l"(gptr) : "memory")
#define CP_COMMIT() asm volatile("cp.async.commit_group;" ::: "memory")
#define CP_WAIT1()  asm volatile("cp.async.wait_group 1;" ::: "memory")
#define CP_WAIT0()  asm volatile("cp.async.wait_group 0;" ::: "memory")

__device__ __forceinline__ uint32_t pack2bf(float a, float b) {
    __nv_bfloat162 t = __floats2bfloat162_rn(a, b);
    return *(uint32_t*)&t;
}

// ---------------- fast exp (FMA pipe) ----------------
__device__ __forceinline__ float fast_exp(float x) {
    x = fmaxf(x, -87.0f);
    float t  = fmaf(x, 1.4426950408889634f, 12582912.0f);
    int   n  = __float_as_int(t) - 0x4B400000;
    float fn = t - 12582912.0f;
    float f  = fmaf(fn, -0.693359375f, x);
    f        = fmaf(fn,  2.12194899e-4f, f);
    float p  = 8.33333377e-3f;
    p = fmaf(p, f, 4.16666679e-2f);
    p = fmaf(p, f, 0.16666667f);
    p = fmaf(p, f, 0.5f);
    p = fmaf(p, f, 1.0f);
    p = fmaf(p, f, 1.0f);
    return __int_as_float(__float_as_int(p) + (n << 23));
}

// ---------------- fused fp32 -> bf16 hi/lo split (all 7 tensors, one launch) ----------------
__global__ void __launch_bounds__(256)
cvt_all_kernel(const float* __restrict__ q, const float* __restrict__ k, const float* __restrict__ v,
               const float* __restrict__ wq, const float* __restrict__ wk,
               const float* __restrict__ wv, const float* __restrict__ wo,
               __nv_bfloat16* __restrict__ inhi, __nv_bfloat16* __restrict__ inlo,
               __nv_bfloat16* __restrict__ whi,  __nv_bfloat16* __restrict__ wlo)
{
    const int t = blockIdx.y;
    const int i = blockIdx.x * blockDim.x + threadIdx.x;
    const float* src;
    __nv_bfloat16 *hi, *lo;
    int n4;
    if (t < 3) {
        n4 = (4096 * 1024) / 4;
        src = (t == 0) ? q : (t == 1) ? k : v;
        hi = inhi + (size_t)t * 4096 * 1024;
        lo = inlo + (size_t)t * 4096 * 1024;
    } else {
        n4 = (1024 * 1024) / 4;
        int w = t - 3;
        src = (w == 0) ? wq : (w == 1) ? wk : (w == 2) ? wv : wo;
        hi = whi + (size_t)w * 1024 * 1024;
        lo = wlo + (size_t)w * 1024 * 1024;
    }
    if (i >= n4) return;
    float4 x = ((const float4*)src)[i];
    __nv_bfloat16 h0 = __float2bfloat16(x.x);
    __nv_bfloat16 h1 = __float2bfloat16(x.y);
    __nv_bfloat16 h2 = __float2bfloat16(x.z);
    __nv_bfloat16 h3 = __float2bfloat16(x.w);
    __nv_bfloat162* H = (__nv_bfloat162*)hi;
    __nv_bfloat162* L = (__nv_bfloat162*)lo;
    H[i * 2]     = __nv_bfloat162(h0, h1);
    H[i * 2 + 1] = __nv_bfloat162(h2, h3);
    L[i * 2]     = __nv_bfloat162(__float2bfloat16(x.x - __bfloat162float(h0)),
                                  __float2bfloat16(x.y - __bfloat162float(h1)));
    L[i * 2 + 1] = __nv_bfloat162(__float2bfloat16(x.z - __bfloat162float(h2)),
                                  __float2bfloat16(x.w - __bfloat162float(h3)));
}

// ---------------- mask prescan ----------------
__global__ void __launch_bounds__(256)
prescan_kernel(const unsigned char* __restrict__ am,
               const unsigned char* __restrict__ kpm,
               int* __restrict__ flags)
{
    const int kt = blockIdx.x, qt = blockIdx.y, b = blockIdx.z;
    const int tid = threadIdx.x;
    unsigned v = 0;
    {
        int q = qt * 64 + (tid >> 2);
        const uint4* p = (const uint4*)(am + ((size_t)(b * SEQC + q)) * SEQC + kt * 64) + (tid & 3);
        uint4 u = *p;
        v = u.x | u.y | u.z | u.w;
    }
    if (tid < 4) {
        const uint4* p = (const uint4*)(kpm + (size_t)b * SEQC + kt * 64) + tid;
        uint4 u = *p;
        v |= u.x | u.y | u.z | u.w;
    }
    #pragma unroll
    for (int off = 16; off >= 1; off >>= 1)
        v |= __shfl_xor_sync(0xffffffffu, v, off);
    __shared__ unsigned wv[8];
    if ((tid & 31) == 0) wv[tid >> 5] = v;
    __syncthreads();
    if (tid == 0) {
        unsigned r = 0;
        #pragma unroll
        for (int w = 0; w < 8; ++w) r |= wv[w];
        flags[(b * 32 + qt) * 32 + kt] = r ? 1 : 0;
    }
}

// ---------------- tensor-core GEMM with cp.async 2-stage pipeline ----------------
#define TSTR 72
#define G_TILE_ELT (128 * TSTR)
#define G_STAGE_ELT (4 * G_TILE_ELT)
#define TCG_SMEM_BYTES (2 * G_STAGE_ELT * 2)
__global__ void __launch_bounds__(256)
tc_gemm_kernel(const __nv_bfloat16* __restrict__ Ahi, const __nv_bfloat16* __restrict__ Alo,
               const __nv_bfloat16* __restrict__ Bhi, const __nv_bfloat16* __restrict__ Blo,
               const float* __restrict__ bias, float* __restrict__ Y,
               __nv_bfloat16* __restrict__ Yhi, __nv_bfloat16* __restrict__ Ylo,
               float scale, int N, int mode)
{
    extern __shared__ __align__(16) __nv_bfloat16 smem[];
    const uint32_t us = smem_u32(smem);

    const int tid  = threadIdx.x;
    const int wid  = tid >> 5, lane = tid & 31;
    const int wm   = wid >> 2, wn = wid & 3;
    const int m0   = blockIdx.y * 128, n0 = blockIdx.x * 128;

    const int r = tid >> 1, hf = tid & 1;
    const size_t a_off = (size_t)(m0 + r) * GKC + hf * 32;
    const size_t b_off = (size_t)(n0 + r) * GKC + hf * 32;
    const uint32_t sto = (uint32_t)(r * TSTR + hf * 32);

    const int a_row  = wm * 64 + (lane & 15);
    const int a_coff = (lane >> 4) << 3;
    const int b_row  = wn * 32 + (lane & 7) + ((lane >> 4) << 3);
    const int b_koff = ((lane >> 3) & 1) << 3;

    float acc[4][4][4] = {};

    auto load_stage = [&](int kt, int s) {
        const int k0 = kt * 64;
        const uint32_t sb = us + (uint32_t)(s * G_STAGE_ELT) * 2;
        #pragma unroll
        for (int c = 0; c < 4; ++c) {
            uint32_t so = (sto + c * 8) * 2;
            CP_ASYNC16(sb + 0 * G_TILE_ELT * 2 + so, Ahi + a_off + k0 + c * 8);
            CP_ASYNC16(sb + 1 * G_TILE_ELT * 2 + so, Alo + a_off + k0 + c * 8);
            CP_ASYNC16(sb + 2 * G_TILE_ELT * 2 + so, Bhi + b_off + k0 + c * 8);
            CP_ASYNC16(sb + 3 * G_TILE_ELT * 2 + so, Blo + b_off + k0 + c * 8);
        }
        CP_COMMIT();
    };

    load_stage(0, 0);
    for (int kt = 0; kt < GKC / 64; ++kt) {
        if (kt + 1 < GKC / 64) { load_stage(kt + 1, (kt + 1) & 1); CP_WAIT1(); }
        else                   { CP_WAIT0(); }
        __syncthreads();

        const uint32_t sb = us + (uint32_t)((kt & 1) * G_STAGE_ELT) * 2;
        const uint32_t uAh = sb, uAl = sb + G_TILE_ELT * 2;
        const uint32_t uBh = sb + 2 * G_TILE_ELT * 2, uBl = sb + 3 * G_TILE_ELT * 2;

        #pragma unroll
        for (int ks = 0; ks < 4; ++ks) {
            const int kc = ks * 16;
            uint32_t Af[4][4], Bh2[2][4], Bl2[2][4];
            #pragma unroll
            for (int mt = 0; mt < 4; ++mt)
                LDSM_X4(Af[mt], uAh + ((a_row + mt * 16) * TSTR + kc + a_coff) * 2);
            #pragma unroll
            for (int nt2 = 0; nt2 < 2; ++nt2) {
                LDSM_X4(Bh2[nt2], uBh + ((b_row + nt2 * 16) * TSTR + kc + b_koff) * 2);
                LDSM_X4(Bl2[nt2], uBl + ((b_row + nt2 * 16) * TSTR + kc + b_koff) * 2);
            }
            #pragma unroll
            for (int mt = 0; mt < 4; ++mt)
                #pragma unroll
                for (int nt = 0; nt < 4; ++nt)
                    MMA16816(acc[mt][nt], Af[mt], Bh2[nt >> 1][(nt & 1) * 2], Bh2[nt >> 1][(nt & 1) * 2 + 1]);
            #pragma unroll
            for (int mt = 0; mt < 4; ++mt)
                #pragma unroll
                for (int nt = 0; nt < 4; ++nt)
                    MMA16816(acc[mt][nt], Af[mt], Bl2[nt >> 1][(nt & 1) * 2], Bl2[nt >> 1][(nt & 1) * 2 + 1]);
            #pragma unroll
            for (int mt = 0; mt < 4; ++mt)
                LDSM_X4(Af[mt], uAl + ((a_row + mt * 16) * TSTR + kc + a_coff) * 2);
            #pragma unroll
            for (int mt = 0; mt < 4; ++mt)
                #pragma unroll
                for (int nt = 0; nt < 4; ++nt)
                    MMA16816(acc[mt][nt], Af[mt], Bh2[nt >> 1][(nt & 1) * 2], Bh2[nt >> 1][(nt & 1) * 2 + 1]);
        }
        __syncthreads();
    }

    const int er = lane >> 2, ec = (lane & 3) * 2;
    #pragma unroll
    for (int mt = 0; mt < 4; ++mt) {
        #pragma unroll
        for (int nt = 0; nt < 4; ++nt) {
            int col  = n0 + wn * 32 + nt * 8 + ec;
            float b0 = __ldg(&bias[col]), b1 = __ldg(&bias[col + 1]);
            #pragma unroll
            for (int half = 0; half < 2; ++half) {
                int m = m0 + wm * 64 + mt * 16 + er + half * 8;
                float vx = (acc[mt][nt][half * 2]     + b0) * scale;
                float vy = (acc[mt][nt][half * 2 + 1] + b1) * scale;
                if (mode == 2) {
                    int bb = m >> 11, s = m & 2047;
                    int hh = col >> 6, dk = col & 63;
                    size_t idx = (((size_t)(bb * NHEADC + hh) * SEQC) + s) * DKC + dk;
                    __nv_bfloat16 hx = __float2bfloat16(vx), hy = __float2bfloat16(vy);
                    *(__nv_bfloat162*)&Yhi[idx] = __nv_bfloat162(hx, hy);
                    *(__nv_bfloat162*)&Ylo[idx] = __nv_bfloat162(
                        __float2bfloat16(vx - __bfloat162float(hx)),
                        __float2bfloat16(vy - __bfloat162float(hy)));
                } else {
                    *(float2*)&Y[(size_t)m * N + col] = make_float2(vx, vy);
                }
            }
        }
    }
}

// ---------------- flash attention on mma.sync + cp.async 2-stage K/V pipeline ----------------
#define ASTR 72
#define A_TILE_ELT (64 * ASTR)
#define A_STAGE_ELT (4 * A_TILE_ELT)
#define ATTN_SMEM_BYTES (2 * A_STAGE_ELT * 2)
__global__ void __launch_bounds__(256)
attn_kernel(const __nv_bfloat16* __restrict__ Qhi, const __nv_bfloat16* __restrict__ Qlo,
            const __nv_bfloat16* __restrict__ Khi, const __nv_bfloat16* __restrict__ Klo,
            const __nv_bfloat16* __restrict__ Vhi, const __nv_bfloat16* __restrict__ Vlo,
            const unsigned char* __restrict__ am,
            const unsigned char* __restrict__ kpm,
            const int* __restrict__ flags,
            __nv_bfloat16* __restrict__ ctxhi, __nv_bfloat16* __restrict__ ctxlo)
{
    extern __shared__ __align__(16) __nv_bfloat16 smem[];
    const uint32_t us = smem_u32(smem);

    const int qt = blockIdx.x;
    const int bh = blockIdx.y;
    const int b  = bh >> 4;
    const int h  = bh & 15;
    const int tid = threadIdx.x;
    const int wid = tid >> 5, lane = tid & 31;
    const int er = lane >> 2, ec = (lane & 3) * 2;

    const size_t qbase = ((size_t)bh * SEQC + qt * 128) * DKC;
    const size_t kvbase = (size_t)bh * SEQC * DKC;

    // ---- stage Q tile via cp.async into stage 0 (Qh at 0, Ql at 128*ASTR) ----
    {
        int r = tid >> 1, hf = tid & 1;
        #pragma unroll
        for (int u = 0; u < 4; ++u) {
            int c = hf * 4 + u;
            uint32_t so = (uint32_t)(r * ASTR + c * 8) * 2;
            CP_ASYNC16(us + so,                     Qhi + qbase + (size_t)r * DKC + c * 8);
            CP_ASYNC16(us + 128 * ASTR * 2 + so,    Qlo + qbase + (size_t)r * DKC + c * 8);
        }
        CP_COMMIT(); CP_WAIT0();
    }
    __syncthreads();

    uint32_t Qh[4][4], Ql[4][4];
    {
        const int a_row  = wid * 16 + (lane & 15);
        const int a_coff = (lane >> 4) << 3;
        #pragma unroll
        for (int ks = 0; ks < 4; ++ks) {
            LDSM_X4(Qh[ks], us + (a_row * ASTR + ks * 16 + a_coff) * 2);
            LDSM_X4(Ql[ks], us + (128 * ASTR + a_row * ASTR + ks * 16 + a_coff) * 2);
        }
    }
    __syncthreads();  // Q fragments extracted; smem free for K/V stages

    const int b_row  = (lane & 7) + ((lane >> 4) << 3);
    const int b_koff = ((lane >> 3) & 1) << 3;
    const int v_row  = (lane & 7) + (((lane >> 3) & 1) << 3);
    const int v_noff = (lane >> 4) << 3;

    auto load_kv = [&](int kt, int s) {
        int r2 = tid >> 2, qc = tid & 3;
        const size_t g = kvbase + (size_t)(kt * 64 + r2) * DKC;
        const uint32_t sb = us + (uint32_t)(s * A_STAGE_ELT) * 2;
        #pragma unroll
        for (int u = 0; u < 2; ++u) {
            int c = qc * 2 + u;
            uint32_t so = (uint32_t)(r2 * ASTR + c * 8) * 2;
            CP_ASYNC16(sb + 0 * A_TILE_ELT * 2 + so, Khi + g + c * 8);
            CP_ASYNC16(sb + 1 * A_TILE_ELT * 2 + so, Klo + g + c * 8);
            CP_ASYNC16(sb + 2 * A_TILE_ELT * 2 + so, Vhi + g + c * 8);
            CP_ASYNC16(sb + 3 * A_TILE_ELT * 2 + so, Vlo + g + c * 8);
        }
        CP_COMMIT();
    };

    float oacc[8][4] = {};
    float m0r = -1e30f, m1r = -1e30f, l0r = 0.f, l1r = 0.f;

    load_kv(0, 0);
    for (int kt = 0; kt < SEQC / 64; ++kt) {
        if (kt + 1 < SEQC / 64) { load_kv(kt + 1, (kt + 1) & 1); CP_WAIT1(); }
        else                    { CP_WAIT0(); }
        __syncthreads();

        const uint32_t sb = us + (uint32_t)((kt & 1) * A_STAGE_ELT) * 2;
        const uint32_t uKh = sb, uKl = sb + A_TILE_ELT * 2;
        const uint32_t uVh = sb + 2 * A_TILE_ELT * 2, uVl = sb + 3 * A_TILE_ELT * 2;

        // ---- S = (Q/8) K^T ----
        float s[8][4] = {};
        #pragma unroll
        for (int ks = 0; ks < 4; ++ks) {
            const int kc = ks * 16;
            uint32_t KB[4][4];
            #pragma unroll
            for (int g = 0; g < 4; ++g)
                LDSM_X4(KB[g], uKh + ((g * 16 + b_row) * ASTR + kc + b_koff) * 2);
            #pragma unroll
            for (int nt = 0; nt < 8; ++nt)
                MMA16816(s[nt], Qh[ks], KB[nt >> 1][(nt & 1) * 2], KB[nt >> 1][(nt & 1) * 2 + 1]);
            #pragma unroll
            for (int nt = 0; nt < 8; ++nt)
                MMA16816(s[nt], Ql[ks], KB[nt >> 1][(nt & 1) * 2], KB[nt >> 1][(nt & 1) * 2 + 1]);
            #pragma unroll
            for (int g = 0; g < 4; ++g)
                LDSM_X4(KB[g], uKl + ((g * 16 + b_row) * ASTR + kc + b_koff) * 2);
            #pragma unroll
            for (int nt = 0; nt < 8; ++nt)
                MMA16816(s[nt], Qh[ks], KB[nt >> 1][(nt & 1) * 2], KB[nt >> 1][(nt & 1) * 2 + 1]);
        }

        // ---- masks (slow path) ----
        int fl = flags[(b * 32 + qt * 2) * 32 + kt] | flags[(b * 32 + qt * 2 + 1) * 32 + kt];
        if (fl) {
            int q0 = qt * 128 + wid * 16 + er;
            #pragma unroll
            for (int nt = 0; nt < 8; ++nt) {
                int kg = kt * 64 + nt * 8 + ec;
                #pragma unroll
                for (int c = 0; c < 4; ++c) {
                    int qg = q0 + (c >> 1) * 8;
                    int kk = kg + (c & 1);
                    if (am[((size_t)(b * SEQC + qg)) * SEQC + kk] | kpm[b * SEQC + kk])
                        s[nt][c] = -1e30f;
                }
            }
        }

        // ---- online softmax ----
        float mx0 = -1e30f, mx1 = -1e30f;
        #pragma unroll
        for (int nt = 0; nt < 8; ++nt) {
            mx0 = fmaxf(mx0, fmaxf(s[nt][0], s[nt][1]));
            mx1 = fmaxf(mx1, fmaxf(s[nt][2], s[nt][3]));
        }
        mx0 = fmaxf(mx0, __shfl_xor_sync(0xffffffffu, mx0, 1));
        mx0 = fmaxf(mx0, __shfl_xor_sync(0xffffffffu, mx0, 2));
        mx1 = fmaxf(mx1, __shfl_xor_sync(0xffffffffu, mx1, 1));
        mx1 = fmaxf(mx1, __shfl_xor_sync(0xffffffffu, mx1, 2));

        float mn0 = fmaxf(m0r, mx0), mn1 = fmaxf(m1r, mx1);
        float al0 = fast_exp(m0r - mn0), al1 = fast_exp(m1r - mn1);
        m0r = mn0; m1r = mn1;

        float sum0 = 0.f, sum1 = 0.f;
        #pragma unroll
        for (int nt = 0; nt < 8; ++nt) {
            float p0 = fast_exp(s[nt][0] - mn0); if (s[nt][0] <= -1e29f) p0 = 0.f;
            float p1 = fast_exp(s[nt][1] - mn0); if (s[nt][1] <= -1e29f) p1 = 0.f;
            float p2 = fast_exp(s[nt][2] - mn1); if (s[nt][2] <= -1e29f) p2 = 0.f;
            float p3 = fast_exp(s[nt][3] - mn1); if (s[nt][3] <= -1e29f) p3 = 0.f;
            s[nt][0] = p0; s[nt][1] = p1; s[nt][2] = p2; s[nt][3] = p3;
            sum0 += p0 + p1; sum1 += p2 + p3;
        }
        sum0 += __shfl_xor_sync(0xffffffffu, sum0, 1);
        sum0 += __shfl_xor_sync(0xffffffffu, sum0, 2);
        sum1 += __shfl_xor_sync(0xffffffffu, sum1, 1);
        sum1 += __shfl_xor_sync(0xffffffffu, sum1, 2);
        l0r = fmaf(l0r, al0, sum0);
        l1r = fmaf(l1r, al1, sum1);
        #pragma unroll
        for (int nt = 0; nt < 8; ++nt) {
            oacc[nt][0] *= al0; oacc[nt][1] *= al0;
            oacc[nt][2] *= al1; oacc[nt][3] *= al1;
        }

        // ---- O += P V (P in registers; C-frag == A-frag layout) ----
        #pragma unroll
        for (int ks = 0; ks < 4; ++ks) {
            const int t0 = 2 * ks, t1 = 2 * ks + 1;
            uint32_t aPh[4], aPl[4];
            {
                float v00 = s[t0][0], v01 = s[t0][1], v02 = s[t0][2], v03 = s[t0][3];
                float v10 = s[t1][0], v11 = s[t1][1], v12 = s[t1][2], v13 = s[t1][3];
                __nv_bfloat16 hh;
                float r00, r01, r02, r03, r10, r11, r12, r13;
                hh = __float2bfloat16(v00); r00 = v00 - __bfloat162float(hh);
                hh = __float2bfloat16(v01); r01 = v01 - __bfloat162float(hh);
                hh = __float2bfloat16(v02); r02 = v02 - __bfloat162float(hh);
                hh = __float2bfloat16(v03); r03 = v03 - __bfloat162float(hh);
                hh = __float2bfloat16(v10); r10 = v10 - __bfloat162float(hh);
                hh = __float2bfloat16(v11); r11 = v11 - __bfloat162float(hh);
                hh = __float2bfloat16(v12); r12 = v12 - __bfloat162float(hh);
                hh = __float2bfloat16(v13); r13 = v13 - __bfloat162float(hh);
                aPh[0] = pack2bf(v00, v01); aPh[1] = pack2bf(v02, v03);
                aPh[2] = pack2bf(v10, v11); aPh[3] = pack2bf(v12, v13);
                aPl[0] = pack2bf(r00, r01); aPl[1] = pack2bf(r02, r03);
                aPl[2] = pack2bf(r10, r11); aPl[3] = pack2bf(r12, r13);
            }
            uint32_t VB[4][4];
            #pragma unroll
            for (int g = 0; g < 4; ++g)
                LDSM_X4_T(VB[g], uVh + ((ks * 16 + v_row) * ASTR + g * 16 + v_noff) * 2);
            #pragma unroll
            for (int nt = 0; nt < 8; ++nt)
                MMA16816(oacc[nt], aPh, VB[nt >> 1][(nt & 1) * 2], VB[nt >> 1][(nt & 1) * 2 + 1]);
            #pragma unroll
            for (int nt = 0; nt < 8; ++nt)
                MMA16816(oacc[nt], aPl, VB[nt >> 1][(nt & 1) * 2], VB[nt >> 1][(nt & 1) * 2 + 1]);
            #pragma unroll
            for (int g = 0; g < 4; ++g)
                LDSM_X4_T(VB[g], uVl + ((ks * 16 + v_row) * ASTR + g * 16 + v_noff) * 2);
            #pragma unroll
            for (int nt = 0; nt < 8; ++nt)
                MMA16816(oacc[nt], aPh, VB[nt >> 1][(nt & 1) * 2], VB[nt >> 1][(nt & 1) * 2 + 1]);
        }
        __syncthreads();
    }

    // ---- epilogue: normalize, write ctx as bf16 hi/lo split ----
    float r0 = (l0r > 0.f) ? (1.0f / l0r) : 0.f;
    float r1 = (l1r > 0.f) ? (1.0f / l1r) : 0.f;
    const int q0 = qt * 128 + wid * 16 + er;
    #pragma unroll
    for (int nt = 0; nt < 8; ++nt) {
        int col = h * DKC + nt * 8 + ec;
        {
            float vx = oacc[nt][0] * r0, vy = oacc[nt][1] * r0;
            size_t idx = ((size_t)(b * SEQC + q0)) * D_MODELC + col;
            __nv_bfloat16 hx = __float2bfloat16(vx), hy = __float2bfloat16(vy);
            *(__nv_bfloat162*)&ctxhi[idx] = __nv_bfloat162(hx, hy);
            *(__nv_bfloat162*)&ctxlo[idx] = __nv_bfloat162(
                __float2bfloat16(vx - __bfloat162float(hx)),
                __float2bfloat16(vy - __bfloat162float(hy)));
        }
        {
            float vx = oacc[nt][2] * r1, vy = oacc[nt][3] * r1;
            size_t idx = ((size_t)(b * SEQC + q0 + 8)) * D_MODELC + col;
            __nv_bfloat16 hx = __float2bfloat16(vx), hy = __float2bfloat16(vy);
            *(__nv_bfloat162*)&ctxhi[idx] = __nv_bfloat162(hx, hy);
            *(__nv_bfloat162*)&ctxlo[idx] = __nv_bfloat162(
                __float2bfloat16(vx - __bfloat162float(hx)),
                __float2bfloat16(vy - __bfloat162float(hy)));
        }
    }
}

// ---------------- launch ----------------
extern "C" void kernel_launch(void* const* d_in, const int* in_sizes, int n_in,
                              void* d_out, int out_size)
{
    const float* query = (const float*)d_in[0];
    const float* key   = (const float*)d_in[1];
    const float* value = (const float*)d_in[2];
    const unsigned char* am  = (const unsigned char*)d_in[3];
    const unsigned char* kpm = (const unsigned char*)d_in[4];
    const float* Wq = (const float*)d_in[5];
    const float* bq = (const float*)d_in[6];
    const float* Wk = (const float*)d_in[7];
    const float* bk = (const float*)d_in[8];
    const float* Wv = (const float*)d_in[9];
    const float* bv = (const float*)d_in[10];
    const float* Wo = (const float*)d_in[11];
    const float* bo = (const float*)d_in[12];
    float* out = (float*)d_out;

    int* flags;
    __nv_bfloat16 *inhi, *inlo, *whi, *wlo, *chi, *clo;
    __nv_bfloat16 *qhi, *qlo, *khi, *klo, *vhi, *vlo;
    cudaGetSymbolAddress((void**)&flags, g_flags);
    cudaGetSymbolAddress((void**)&inhi,  g_inhi);
    cudaGetSymbolAddress((void**)&inlo,  g_inlo);
    cudaGetSymbolAddress((void**)&whi,   g_whi);
    cudaGetSymbolAddress((void**)&wlo,   g_wlo);
    cudaGetSymbolAddress((void**)&chi,   g_chi);
    cudaGetSymbolAddress((void**)&clo,   g_clo);
    cudaGetSymbolAddress((void**)&qhi,   g_qhi);
    cudaGetSymbolAddress((void**)&qlo,   g_qlo);
    cudaGetSymbolAddress((void**)&khi,   g_khi);
    cudaGetSymbolAddress((void**)&klo,   g_klo);
    cudaGetSymbolAddress((void**)&vhi,   g_vhi);
    cudaGetSymbolAddress((void**)&vlo,   g_vlo);

    static int attr_set = 0;
    if (!attr_set) {
        cudaFuncSetAttribute(attn_kernel, cudaFuncAttributeMaxDynamicSharedMemorySize, ATTN_SMEM_BYTES);
        cudaFuncSetAttribute(tc_gemm_kernel, cudaFuncAttributeMaxDynamicSharedMemorySize, TCG_SMEM_BYTES);
        attr_set = 1;
    }

    // launch 1: prescan
    dim3 pg(32, 32, 2);
    prescan_kernel<<<pg, 256>>>(am, kpm, flags);

    // launch 2: all conversions fused
    dim3 cg(4096, 7);
    cvt_all_kernel<<<cg, 256>>>(query, key, value, Wq, Wk, Wv, Wo, inhi, inlo, whi, wlo);

    // launches 3-5: Q/K/V projections
    const int IN_N = 4096 * 1024, W_N = 1024 * 1024;
    dim3 gg(8, 32);
    tc_gemm_kernel<<<gg, 256, TCG_SMEM_BYTES>>>(inhi,            inlo,            whi,           wlo,           bq, nullptr, qhi, qlo, 0.125f, 1024, 2);
    tc_gemm_kernel<<<gg, 256, TCG_SMEM_BYTES>>>(inhi + IN_N,     inlo + IN_N,     whi + W_N,     wlo + W_N,     bk, nullptr, khi, klo, 1.0f,   1024, 2);
    tc_gemm_kernel<<<gg, 256, TCG_SMEM_BYTES>>>(inhi + 2 * IN_N, inlo + 2 * IN_N, whi + 2 * W_N, wlo + 2 * W_N, bv, nullptr, vhi, vlo, 1.0f,   1024, 2);

    // launch 6 (ncu -s 5 -c 1 profiles this one): attention
    dim3 ag(16, 32);
    attn_kernel<<<ag, 256, ATTN_SMEM_BYTES>>>(qhi, qlo, khi, klo, vhi, vlo, am, kpm, flags, chi, clo);

    // launch 7: output projection
    tc_gemm_kernel<<<gg, 256, TCG_SMEM_BYTES>>>(chi, clo, whi + 3 * W_N, wlo + 3 * W_N, bo, out, nullptr, nullptr, 1.0f, 1024, 0);
}

// round 13
// speedup vs baseline: 2.6464x; 1.0723x over previous
#include <cuda_runtime.h>
#include <cuda_bf16.h>
#include <cstdint>
#include <cstddef>

#define D_MODELC 1024
#define NHEADC   16
#define DKC      64
#define SEQC     2048
#define BATCHC   2
#define GKC      1024

// ---------------- device scratch (allocation-free) ----------------
__device__ int g_flags[BATCHC * 32 * 32];

__device__ __nv_bfloat16 g_inhi[3 * 4096 * 1024];
__device__ __nv_bfloat16 g_inlo[3 * 4096 * 1024];
__device__ __nv_bfloat16 g_whi[4 * 1024 * 1024];
__device__ __nv_bfloat16 g_wlo[4 * 1024 * 1024];
__device__ __nv_bfloat16 g_qhi[BATCHC * NHEADC * SEQC * DKC];
__device__ __nv_bfloat16 g_qlo[BATCHC * NHEADC * SEQC * DKC];
__device__ __nv_bfloat16 g_khi[BATCHC * NHEADC * SEQC * DKC];
__device__ __nv_bfloat16 g_klo[BATCHC * NHEADC * SEQC * DKC];
__device__ __nv_bfloat16 g_vhi[BATCHC * NHEADC * SEQC * DKC];
__device__ __nv_bfloat16 g_vlo[BATCHC * NHEADC * SEQC * DKC];
__device__ __nv_bfloat16 g_chi[4096 * 1024];
__device__ __nv_bfloat16 g_clo[4096 * 1024];

// ---------------- helpers ----------------
__device__ __forceinline__ uint32_t smem_u32(const void* p) {
    uint32_t a;
    asm("{ .reg .u64 t; cvta.to.shared.u64 t, %1; cvt.u32.u64 %0, t; }" : "=r"(a) : "l"(p));
    return a;
}
#define LDSM_X4(R, addr) \
    asm volatile("ldmatrix.sync.aligned.m8n8.x4.shared.b16 {%0,%1,%2,%3}, [%4];" \
        : "=r"((R)[0]), "=r"((R)[1]), "=r"((R)[2]), "=r"((R)[3]) : "r"(addr))
#define LDSM_X4_T(R, addr) \
    asm volatile("ldmatrix.sync.aligned.m8n8.x4.trans.shared.b16 {%0,%1,%2,%3}, [%4];" \
        : "=r"((R)[0]), "=r"((R)[1]), "=r"((R)[2]), "=r"((R)[3]) : "r"(addr))
#define MMA16816(C, A, B0, B1) \
    asm volatile("mma.sync.aligned.m16n8k16.row.col.f32.bf16.bf16.f32 " \
        "{%0,%1,%2,%3}, {%4,%5,%6,%7}, {%8,%9}, {%0,%1,%2,%3};" \
        : "+f"((C)[0]), "+f"((C)[1]), "+f"((C)[2]), "+f"((C)[3]) \
        : "r"((A)[0]), "r"((A)[1]), "r"((A)[2]), "r"((A)[3]), "r"(B0), "r"(B1))
#define CP_ASYNC16(saddr, gptr) \
    asm volatile("cp.async.cg.shared.global [%0], [%1], 16;" :: "r"(saddr), "l"(gptr) : "memory")
#define CP_COMMIT() asm volatile("cp.async.commit_group;" ::: "memory")
#define CP_WAIT1()  asm volatile("cp.async.wait_group 1;" ::: "memory")
#define CP_WAIT0()  asm volatile("cp.async.wait_group 0;" ::: "memory")

__device__ __forceinline__ uint32_t pack2bf(float a, float b) {
    __nv_bfloat162 t = __floats2bfloat162_rn(a, b);
    return *(uint32_t*)&t;
}

// ---------------- fast exp (FMA pipe) ----------------
__device__ __forceinline__ float fast_exp(float x) {
    x = fmaxf(x, -87.0f);
    float t  = fmaf(x, 1.4426950408889634f, 12582912.0f);
    int   n  = __float_as_int(t) - 0x4B400000;
    float fn = t - 12582912.0f;
    float f  = fmaf(fn, -0.693359375f, x);
    f        = fmaf(fn,  2.12194899e-4f, f);
    float p  = 8.33333377e-3f;
    p = fmaf(p, f, 4.16666679e-2f);
    p = fmaf(p, f, 0.16666667f);
    p = fmaf(p, f, 0.5f);
    p = fmaf(p, f, 1.0f);
    p = fmaf(p, f, 1.0f);
    return __int_as_float(__float_as_int(p) + (n << 23));
}

// ---------------- fused fp32 -> bf16 hi/lo split ----------------
__global__ void __launch_bounds__(256)
cvt_all_kernel(const float* __restrict__ q, const float* __restrict__ k, const float* __restrict__ v,
               const float* __restrict__ wq, const float* __restrict__ wk,
               const float* __restrict__ wv, const float* __restrict__ wo,
               __nv_bfloat16* __restrict__ inhi, __nv_bfloat16* __restrict__ inlo,
               __nv_bfloat16* __restrict__ whi,  __nv_bfloat16* __restrict__ wlo)
{
    const int t = blockIdx.y;
    const int i = blockIdx.x * blockDim.x + threadIdx.x;
    const float* src;
    __nv_bfloat16 *hi, *lo;
    int n4;
    if (t < 3) {
        n4 = (4096 * 1024) / 4;
        src = (t == 0) ? q : (t == 1) ? k : v;
        hi = inhi + (size_t)t * 4096 * 1024;
        lo = inlo + (size_t)t * 4096 * 1024;
    } else {
        n4 = (1024 * 1024) / 4;
        int w = t - 3;
        src = (w == 0) ? wq : (w == 1) ? wk : (w == 2) ? wv : wo;
        hi = whi + (size_t)w * 1024 * 1024;
        lo = wlo + (size_t)w * 1024 * 1024;
    }
    if (i >= n4) return;
    float4 x = ((const float4*)src)[i];
    __nv_bfloat16 h0 = __float2bfloat16(x.x);
    __nv_bfloat16 h1 = __float2bfloat16(x.y);
    __nv_bfloat16 h2 = __float2bfloat16(x.z);
    __nv_bfloat16 h3 = __float2bfloat16(x.w);
    __nv_bfloat162* H = (__nv_bfloat162*)hi;
    __nv_bfloat162* L = (__nv_bfloat162*)lo;
    H[i * 2]     = __nv_bfloat162(h0, h1);
    H[i * 2 + 1] = __nv_bfloat162(h2, h3);
    L[i * 2]     = __nv_bfloat162(__float2bfloat16(x.x - __bfloat162float(h0)),
                                  __float2bfloat16(x.y - __bfloat162float(h1)));
    L[i * 2 + 1] = __nv_bfloat162(__float2bfloat16(x.z - __bfloat162float(h2)),
                                  __float2bfloat16(x.w - __bfloat162float(h3)));
}

// ---------------- mask prescan ----------------
__global__ void __launch_bounds__(256)
prescan_kernel(const unsigned char* __restrict__ am,
               const unsigned char* __restrict__ kpm,
               int* __restrict__ flags)
{
    const int kt = blockIdx.x, qt = blockIdx.y, b = blockIdx.z;
    const int tid = threadIdx.x;
    unsigned v = 0;
    {
        int q = qt * 64 + (tid >> 2);
        const uint4* p = (const uint4*)(am + ((size_t)(b * SEQC + q)) * SEQC + kt * 64) + (tid & 3);
        uint4 u = *p;
        v = u.x | u.y | u.z | u.w;
    }
    if (tid < 4) {
        const uint4* p = (const uint4*)(kpm + (size_t)b * SEQC + kt * 64) + tid;
        uint4 u = *p;
        v |= u.x | u.y | u.z | u.w;
    }
    #pragma unroll
    for (int off = 16; off >= 1; off >>= 1)
        v |= __shfl_xor_sync(0xffffffffu, v, off);
    __shared__ unsigned wv[8];
    if ((tid & 31) == 0) wv[tid >> 5] = v;
    __syncthreads();
    if (tid == 0) {
        unsigned r = 0;
        #pragma unroll
        for (int w = 0; w < 8; ++w) r |= wv[w];
        flags[(b * 32 + qt) * 32 + kt] = r ? 1 : 0;
    }
}

// ---------------- tensor-core GEMM: BK=32 2-stage cp.async, 2 CTAs/SM ----------------
#define TSTR 40
#define G_TILE_ELT (128 * TSTR)
#define G_STAGE_ELT (4 * G_TILE_ELT)
#define TCG_SMEM_BYTES (2 * G_STAGE_ELT * 2)   // 81920 B
__global__ void __launch_bounds__(256, 2)
tc_gemm_kernel(const __nv_bfloat16* __restrict__ Ahi, const __nv_bfloat16* __restrict__ Alo,
               const __nv_bfloat16* __restrict__ Bhi, const __nv_bfloat16* __restrict__ Blo,
               const float* __restrict__ bias, float* __restrict__ Y,
               __nv_bfloat16* __restrict__ Yhi, __nv_bfloat16* __restrict__ Ylo,
               float scale, int N, int mode)
{
    extern __shared__ __align__(16) __nv_bfloat16 smem[];
    const uint32_t us = smem_u32(smem);

    const int tid  = threadIdx.x;
    const int wid  = tid >> 5, lane = tid & 31;
    const int wm   = wid >> 2, wn = wid & 3;
    const int m0   = blockIdx.y * 128, n0 = blockIdx.x * 128;

    const int r = tid >> 1, hf = tid & 1;
    const size_t a_off = (size_t)(m0 + r) * GKC + hf * 16;
    const size_t b_off = (size_t)(n0 + r) * GKC + hf * 16;
    const uint32_t sto = (uint32_t)(r * TSTR + hf * 16);

    const int a_row  = wm * 64 + (lane & 15);
    const int a_coff = (lane >> 4) << 3;
    const int b_row  = wn * 32 + (lane & 7) + ((lane >> 4) << 3);
    const int b_koff = ((lane >> 3) & 1) << 3;

    float acc[4][4][4] = {};

    auto load_stage = [&](int kt, int s) {
        const int k0 = kt * 32;
        const uint32_t sb = us + (uint32_t)(s * G_STAGE_ELT) * 2;
        #pragma unroll
        for (int c = 0; c < 2; ++c) {
            uint32_t so = (sto + c * 8) * 2;
            CP_ASYNC16(sb + 0 * G_TILE_ELT * 2 + so, Ahi + a_off + k0 + c * 8);
            CP_ASYNC16(sb + 1 * G_TILE_ELT * 2 + so, Alo + a_off + k0 + c * 8);
            CP_ASYNC16(sb + 2 * G_TILE_ELT * 2 + so, Bhi + b_off + k0 + c * 8);
            CP_ASYNC16(sb + 3 * G_TILE_ELT * 2 + so, Blo + b_off + k0 + c * 8);
        }
        CP_COMMIT();
    };

    load_stage(0, 0);
    for (int kt = 0; kt < GKC / 32; ++kt) {
        if (kt + 1 < GKC / 32) { load_stage(kt + 1, (kt + 1) & 1); CP_WAIT1(); }
        else                   { CP_WAIT0(); }
        __syncthreads();

        const uint32_t sb = us + (uint32_t)((kt & 1) * G_STAGE_ELT) * 2;
        const uint32_t uAh = sb, uAl = sb + G_TILE_ELT * 2;
        const uint32_t uBh = sb + 2 * G_TILE_ELT * 2, uBl = sb + 3 * G_TILE_ELT * 2;

        #pragma unroll
        for (int ks = 0; ks < 2; ++ks) {
            const int kc = ks * 16;
            uint32_t Af[4][4], Bh2[2][4], Bl2[2][4];
            #pragma unroll
            for (int mt = 0; mt < 4; ++mt)
                LDSM_X4(Af[mt], uAh + ((a_row + mt * 16) * TSTR + kc + a_coff) * 2);
            #pragma unroll
            for (int nt2 = 0; nt2 < 2; ++nt2) {
                LDSM_X4(Bh2[nt2], uBh + ((b_row + nt2 * 16) * TSTR + kc + b_koff) * 2);
                LDSM_X4(Bl2[nt2], uBl + ((b_row + nt2 * 16) * TSTR + kc + b_koff) * 2);
            }
            #pragma unroll
            for (int mt = 0; mt < 4; ++mt)
                #pragma unroll
                for (int nt = 0; nt < 4; ++nt)
                    MMA16816(acc[mt][nt], Af[mt], Bh2[nt >> 1][(nt & 1) * 2], Bh2[nt >> 1][(nt & 1) * 2 + 1]);
            #pragma unroll
            for (int mt = 0; mt < 4; ++mt)
                #pragma unroll
                for (int nt = 0; nt < 4; ++nt)
                    MMA16816(acc[mt][nt], Af[mt], Bl2[nt >> 1][(nt & 1) * 2], Bl2[nt >> 1][(nt & 1) * 2 + 1]);
            #pragma unroll
            for (int mt = 0; mt < 4; ++mt)
                LDSM_X4(Af[mt], uAl + ((a_row + mt * 16) * TSTR + kc + a_coff) * 2);
            #pragma unroll
            for (int mt = 0; mt < 4; ++mt)
                #pragma unroll
                for (int nt = 0; nt < 4; ++nt)
                    MMA16816(acc[mt][nt], Af[mt], Bh2[nt >> 1][(nt & 1) * 2], Bh2[nt >> 1][(nt & 1) * 2 + 1]);
        }
        __syncthreads();
    }

    const int er = lane >> 2, ec = (lane & 3) * 2;
    #pragma unroll
    for (int mt = 0; mt < 4; ++mt) {
        #pragma unroll
        for (int nt = 0; nt < 4; ++nt) {
            int col  = n0 + wn * 32 + nt * 8 + ec;
            float b0 = __ldg(&bias[col]), b1 = __ldg(&bias[col + 1]);
            #pragma unroll
            for (int half = 0; half < 2; ++half) {
                int m = m0 + wm * 64 + mt * 16 + er + half * 8;
                float vx = (acc[mt][nt][half * 2]     + b0) * scale;
                float vy = (acc[mt][nt][half * 2 + 1] + b1) * scale;
                if (mode == 2) {
                    int bb = m >> 11, s = m & 2047;
                    int hh = col >> 6, dk = col & 63;
                    size_t idx = (((size_t)(bb * NHEADC + hh) * SEQC) + s) * DKC + dk;
                    __nv_bfloat16 hx = __float2bfloat16(vx), hy = __float2bfloat16(vy);
                    *(__nv_bfloat162*)&Yhi[idx] = __nv_bfloat162(hx, hy);
                    *(__nv_bfloat162*)&Ylo[idx] = __nv_bfloat162(
                        __float2bfloat16(vx - __bfloat162float(hx)),
                        __float2bfloat16(vy - __bfloat162float(hy)));
                } else {
                    *(float2*)&Y[(size_t)m * N + col] = make_float2(vx, vy);
                }
            }
        }
    }
}

// ---------------- flash attention on mma.sync + cp.async 2-stage K/V pipeline ----------------
#define ASTR 72
#define A_TILE_ELT (64 * ASTR)
#define A_STAGE_ELT (4 * A_TILE_ELT)
#define ATTN_SMEM_BYTES (2 * A_STAGE_ELT * 2)
__global__ void __launch_bounds__(256)
attn_kernel(const __nv_bfloat16* __restrict__ Qhi, const __nv_bfloat16* __restrict__ Qlo,
            const __nv_bfloat16* __restrict__ Khi, const __nv_bfloat16* __restrict__ Klo,
            const __nv_bfloat16* __restrict__ Vhi, const __nv_bfloat16* __restrict__ Vlo,
            const unsigned char* __restrict__ am,
            const unsigned char* __restrict__ kpm,
            const int* __restrict__ flags,
            __nv_bfloat16* __restrict__ ctxhi, __nv_bfloat16* __restrict__ ctxlo)
{
    extern __shared__ __align__(16) __nv_bfloat16 smem[];
    const uint32_t us = smem_u32(smem);

    const int qt = blockIdx.x;
    const int bh = blockIdx.y;
    const int b  = bh >> 4;
    const int h  = bh & 15;
    const int tid = threadIdx.x;
    const int wid = tid >> 5, lane = tid & 31;
    const int er = lane >> 2, ec = (lane & 3) * 2;

    const size_t qbase = ((size_t)bh * SEQC + qt * 128) * DKC;
    const size_t kvbase = (size_t)bh * SEQC * DKC;

    {
        int r = tid >> 1, hf = tid & 1;
        #pragma unroll
        for (int u = 0; u < 4; ++u) {
            int c = hf * 4 + u;
            uint32_t so = (uint32_t)(r * ASTR + c * 8) * 2;
            CP_ASYNC16(us + so,                     Qhi + qbase + (size_t)r * DKC + c * 8);
            CP_ASYNC16(us + 128 * ASTR * 2 + so,    Qlo + qbase + (size_t)r * DKC + c * 8);
        }
        CP_COMMIT(); CP_WAIT0();
    }
    __syncthreads();

    uint32_t Qh[4][4], Ql[4][4];
    {
        const int a_row  = wid * 16 + (lane & 15);
        const int a_coff = (lane >> 4) << 3;
        #pragma unroll
        for (int ks = 0; ks < 4; ++ks) {
            LDSM_X4(Qh[ks], us + (a_row * ASTR + ks * 16 + a_coff) * 2);
            LDSM_X4(Ql[ks], us + (128 * ASTR + a_row * ASTR + ks * 16 + a_coff) * 2);
        }
    }
    __syncthreads();

    const int b_row  = (lane & 7) + ((lane >> 4) << 3);
    const int b_koff = ((lane >> 3) & 1) << 3;
    const int v_row  = (lane & 7) + (((lane >> 3) & 1) << 3);
    const int v_noff = (lane >> 4) << 3;

    auto load_kv = [&](int kt, int s) {
        int r2 = tid >> 2, qc = tid & 3;
        const size_t g = kvbase + (size_t)(kt * 64 + r2) * DKC;
        const uint32_t sb = us + (uint32_t)(s * A_STAGE_ELT) * 2;
        #pragma unroll
        for (int u = 0; u < 2; ++u) {
            int c = qc * 2 + u;
            uint32_t so = (uint32_t)(r2 * ASTR + c * 8) * 2;
            CP_ASYNC16(sb + 0 * A_TILE_ELT * 2 + so, Khi + g + c * 8);
            CP_ASYNC16(sb + 1 * A_TILE_ELT * 2 + so, Klo + g + c * 8);
            CP_ASYNC16(sb + 2 * A_TILE_ELT * 2 + so, Vhi + g + c * 8);
            CP_ASYNC16(sb + 3 * A_TILE_ELT * 2 + so, Vlo + g + c * 8);
        }
        CP_COMMIT();
    };

    float oacc[8][4] = {};
    float m0r = -1e30f, m1r = -1e30f, l0r = 0.f, l1r = 0.f;

    load_kv(0, 0);
    for (int kt = 0; kt < SEQC / 64; ++kt) {
        if (kt + 1 < SEQC / 64) { load_kv(kt + 1, (kt + 1) & 1); CP_WAIT1(); }
        else                    { CP_WAIT0(); }
        __syncthreads();

        const uint32_t sb = us + (uint32_t)((kt & 1) * A_STAGE_ELT) * 2;
        const uint32_t uKh = sb, uKl = sb + A_TILE_ELT * 2;
        const uint32_t uVh = sb + 2 * A_TILE_ELT * 2, uVl = sb + 3 * A_TILE_ELT * 2;

        float s[8][4] = {};
        #pragma unroll
        for (int ks = 0; ks < 4; ++ks) {
            const int kc = ks * 16;
            uint32_t KB[4][4];
            #pragma unroll
            for (int g = 0; g < 4; ++g)
                LDSM_X4(KB[g], uKh + ((g * 16 + b_row) * ASTR + kc + b_koff) * 2);
            #pragma unroll
            for (int nt = 0; nt < 8; ++nt)
                MMA16816(s[nt], Qh[ks], KB[nt >> 1][(nt & 1) * 2], KB[nt >> 1][(nt & 1) * 2 + 1]);
            #pragma unroll
            for (int nt = 0; nt < 8; ++nt)
                MMA16816(s[nt], Ql[ks], KB[nt >> 1][(nt & 1) * 2], KB[nt >> 1][(nt & 1) * 2 + 1]);
            #pragma unroll
            for (int g = 0; g < 4; ++g)
                LDSM_X4(KB[g], uKl + ((g * 16 + b_row) * ASTR + kc + b_koff) * 2);
            #pragma unroll
            for (int nt = 0; nt < 8; ++nt)
                MMA16816(s[nt], Qh[ks], KB[nt >> 1][(nt & 1) * 2], KB[nt >> 1][(nt & 1) * 2 + 1]);
        }

        int fl = flags[(b * 32 + qt * 2) * 32 + kt] | flags[(b * 32 + qt * 2 + 1) * 32 + kt];
        if (fl) {
            int q0 = qt * 128 + wid * 16 + er;
            #pragma unroll
            for (int nt = 0; nt < 8; ++nt) {
                int kg = kt * 64 + nt * 8 + ec;
                #pragma unroll
                for (int c = 0; c < 4; ++c) {
                    int qg = q0 + (c >> 1) * 8;
                    int kk = kg + (c & 1);
                    if (am[((size_t)(b * SEQC + qg)) * SEQC + kk] | kpm[b * SEQC + kk])
                        s[nt][c] = -1e30f;
                }
            }
        }

        float mx0 = -1e30f, mx1 = -1e30f;
        #pragma unroll
        for (int nt = 0; nt < 8; ++nt) {
            mx0 = fmaxf(mx0, fmaxf(s[nt][0], s[nt][1]));
            mx1 = fmaxf(mx1, fmaxf(s[nt][2], s[nt][3]));
        }
        mx0 = fmaxf(mx0, __shfl_xor_sync(0xffffffffu, mx0, 1));
        mx0 = fmaxf(mx0, __shfl_xor_sync(0xffffffffu, mx0, 2));
        mx1 = fmaxf(mx1, __shfl_xor_sync(0xffffffffu, mx1, 1));
        mx1 = fmaxf(mx1, __shfl_xor_sync(0xffffffffu, mx1, 2));

        float mn0 = fmaxf(m0r, mx0), mn1 = fmaxf(m1r, mx1);
        float al0 = fast_exp(m0r - mn0), al1 = fast_exp(m1r - mn1);
        m0r = mn0; m1r = mn1;

        float sum0 = 0.f, sum1 = 0.f;
        #pragma unroll
        for (int nt = 0; nt < 8; ++nt) {
            float p0 = fast_exp(s[nt][0] - mn0); if (s[nt][0] <= -1e29f) p0 = 0.f;
            float p1 = fast_exp(s[nt][1] - mn0); if (s[nt][1] <= -1e29f) p1 = 0.f;
            float p2 = fast_exp(s[nt][2] - mn1); if (s[nt][2] <= -1e29f) p2 = 0.f;
            float p3 = fast_exp(s[nt][3] - mn1); if (s[nt][3] <= -1e29f) p3 = 0.f;
            s[nt][0] = p0; s[nt][1] = p1; s[nt][2] = p2; s[nt][3] = p3;
            sum0 += p0 + p1; sum1 += p2 + p3;
        }
        sum0 += __shfl_xor_sync(0xffffffffu, sum0, 1);
        sum0 += __shfl_xor_sync(0xffffffffu, sum0, 2);
        sum1 += __shfl_xor_sync(0xffffffffu, sum1, 1);
        sum1 += __shfl_xor_sync(0xffffffffu, sum1, 2);
        l0r = fmaf(l0r, al0, sum0);
        l1r = fmaf(l1r, al1, sum1);
        #pragma unroll
        for (int nt = 0; nt < 8; ++nt) {
            oacc[nt][0] *= al0; oacc[nt][1] *= al0;
            oacc[nt][2] *= al1; oacc[nt][3] *= al1;
        }

        #pragma unroll
        for (int ks = 0; ks < 4; ++ks) {
            const int t0 = 2 * ks, t1 = 2 * ks + 1;
            uint32_t aPh[4], aPl[4];
            {
                float v00 = s[t0][0], v01 = s[t0][1], v02 = s[t0][2], v03 = s[t0][3];
                float v10 = s[t1][0], v11 = s[t1][1], v12 = s[t1][2], v13 = s[t1][3];
                __nv_bfloat16 hh;
                float r00, r01, r02, r03, r10, r11, r12, r13;
                hh = __float2bfloat16(v00); r00 = v00 - __bfloat162float(hh);
                hh = __float2bfloat16(v01); r01 = v01 - __bfloat162float(hh);
                hh = __float2bfloat16(v02); r02 = v02 - __bfloat162float(hh);
                hh = __float2bfloat16(v03); r03 = v03 - __bfloat162float(hh);
                hh = __float2bfloat16(v10); r10 = v10 - __bfloat162float(hh);
                hh = __float2bfloat16(v11); r11 = v11 - __bfloat162float(hh);
                hh = __float2bfloat16(v12); r12 = v12 - __bfloat162float(hh);
                hh = __float2bfloat16(v13); r13 = v13 - __bfloat162float(hh);
                aPh[0] = pack2bf(v00, v01); aPh[1] = pack2bf(v02, v03);
                aPh[2] = pack2bf(v10, v11); aPh[3] = pack2bf(v12, v13);
                aPl[0] = pack2bf(r00, r01); aPl[1] = pack2bf(r02, r03);
                aPl[2] = pack2bf(r10, r11); aPl[3] = pack2bf(r12, r13);
            }
            uint32_t VB[4][4];
            #pragma unroll
            for (int g = 0; g < 4; ++g)
                LDSM_X4_T(VB[g], uVh + ((ks * 16 + v_row) * ASTR + g * 16 + v_noff) * 2);
            #pragma unroll
            for (int nt = 0; nt < 8; ++nt)
                MMA16816(oacc[nt], aPh, VB[nt >> 1][(nt & 1) * 2], VB[nt >> 1][(nt & 1) * 2 + 1]);
            #pragma unroll
            for (int nt = 0; nt < 8; ++nt)
                MMA16816(oacc[nt], aPl, VB[nt >> 1][(nt & 1) * 2], VB[nt >> 1][(nt & 1) * 2 + 1]);
            #pragma unroll
            for (int g = 0; g < 4; ++g)
                LDSM_X4_T(VB[g], uVl + ((ks * 16 + v_row) * ASTR + g * 16 + v_noff) * 2);
            #pragma unroll
            for (int nt = 0; nt < 8; ++nt)
                MMA16816(oacc[nt], aPh, VB[nt >> 1][(nt & 1) * 2], VB[nt >> 1][(nt & 1) * 2 + 1]);
        }
        __syncthreads();
    }

    float r0 = (l0r > 0.f) ? (1.0f / l0r) : 0.f;
    float r1 = (l1r > 0.f) ? (1.0f / l1r) : 0.f;
    const int q0 = qt * 128 + wid * 16 + er;
    #pragma unroll
    for (int nt = 0; nt < 8; ++nt) {
        int col = h * DKC + nt * 8 + ec;
        {
            float vx = oacc[nt][0] * r0, vy = oacc[nt][1] * r0;
            size_t idx = ((size_t)(b * SEQC + q0)) * D_MODELC + col;
            __nv_bfloat16 hx = __float2bfloat16(vx), hy = __float2bfloat16(vy);
            *(__nv_bfloat162*)&ctxhi[idx] = __nv_bfloat162(hx, hy);
            *(__nv_bfloat162*)&ctxlo[idx] = __nv_bfloat162(
                __float2bfloat16(vx - __bfloat162float(hx)),
                __float2bfloat16(vy - __bfloat162float(hy)));
        }
        {
            float vx = oacc[nt][2] * r1, vy = oacc[nt][3] * r1;
            size_t idx = ((size_t)(b * SEQC + q0 + 8)) * D_MODELC + col;
            __nv_bfloat16 hx = __float2bfloat16(vx), hy = __float2bfloat16(vy);
            *(__nv_bfloat162*)&ctxhi[idx] = __nv_bfloat162(hx, hy);
            *(__nv_bfloat162*)&ctxlo[idx] = __nv_bfloat162(
                __float2bfloat16(vx - __bfloat162float(hx)),
                __float2bfloat16(vy - __bfloat162float(hy)));
        }
    }
}

// ---------------- launch ----------------
extern "C" void kernel_launch(void* const* d_in, const int* in_sizes, int n_in,
                              void* d_out, int out_size)
{
    const float* query = (const float*)d_in[0];
    const float* key   = (const float*)d_in[1];
    const float* value = (const float*)d_in[2];
    const unsigned char* am  = (const unsigned char*)d_in[3];
    const unsigned char* kpm = (const unsigned char*)d_in[4];
    const float* Wq = (const float*)d_in[5];
    const float* bq = (const float*)d_in[6];
    const float* Wk = (const float*)d_in[7];
    const float* bk = (const float*)d_in[8];
    const float* Wv = (const float*)d_in[9];
    const float* bv = (const float*)d_in[10];
    const float* Wo = (const float*)d_in[11];
    const float* bo = (const float*)d_in[12];
    float* out = (float*)d_out;

    int* flags;
    __nv_bfloat16 *inhi, *inlo, *whi, *wlo, *chi, *clo;
    __nv_bfloat16 *qhi, *qlo, *khi, *klo, *vhi, *vlo;
    cudaGetSymbolAddress((void**)&flags, g_flags);
    cudaGetSymbolAddress((void**)&inhi,  g_inhi);
    cudaGetSymbolAddress((void**)&inlo,  g_inlo);
    cudaGetSymbolAddress((void**)&whi,   g_whi);
    cudaGetSymbolAddress((void**)&wlo,   g_wlo);
    cudaGetSymbolAddress((void**)&chi,   g_chi);
    cudaGetSymbolAddress((void**)&clo,   g_clo);
    cudaGetSymbolAddress((void**)&qhi,   g_qhi);
    cudaGetSymbolAddress((void**)&qlo,   g_qlo);
    cudaGetSymbolAddress((void**)&khi,   g_khi);
    cudaGetSymbolAddress((void**)&klo,   g_klo);
    cudaGetSymbolAddress((void**)&vhi,   g_vhi);
    cudaGetSymbolAddress((void**)&vlo,   g_vlo);

    static int attr_set = 0;
    if (!attr_set) {
        cudaFuncSetAttribute(attn_kernel, cudaFuncAttributeMaxDynamicSharedMemorySize, ATTN_SMEM_BYTES);
        cudaFuncSetAttribute(tc_gemm_kernel, cudaFuncAttributeMaxDynamicSharedMemorySize, TCG_SMEM_BYTES);
        attr_set = 1;
    }

    // launch 1: prescan
    dim3 pg(32, 32, 2);
    prescan_kernel<<<pg, 256>>>(am, kpm, flags);

    // launch 2: all conversions fused
    dim3 cg(4096, 7);
    cvt_all_kernel<<<cg, 256>>>(query, key, value, Wq, Wk, Wv, Wo, inhi, inlo, whi, wlo);

    // launches 3-5: Q/K/V projections (each now a single wave at 2 CTAs/SM)
    const int IN_N = 4096 * 1024, W_N = 1024 * 1024;
    dim3 gg(8, 32);
    tc_gemm_kernel<<<gg, 256, TCG_SMEM_BYTES>>>(inhi,            inlo,            whi,           wlo,           bq, nullptr, qhi, qlo, 0.125f, 1024, 2);
    tc_gemm_kernel<<<gg, 256, TCG_SMEM_BYTES>>>(inhi + IN_N,     inlo + IN_N,     whi + W_N,     wlo + W_N,     bk, nullptr, khi, klo, 1.0f,   1024, 2);
    tc_gemm_kernel<<<gg, 256, TCG_SMEM_BYTES>>>(inhi + 2 * IN_N, inlo + 2 * IN_N, whi + 2 * W_N, wlo + 2 * W_N, bv, nullptr, vhi, vlo, 1.0f,   1024, 2);

    // launch 6 (ncu -s 5 -c 1 profiles this one): attention
    dim3 ag(16, 32);
    attn_kernel<<<ag, 256, ATTN_SMEM_BYTES>>>(qhi, qlo, khi, klo, vhi, vlo, am, kpm, flags, chi, clo);

    // launch 7: output projection
    tc_gemm_kernel<<<gg, 256, TCG_SMEM_BYTES>>>(chi, clo, whi + 3 * W_N, wlo + 3 * W_N, bo, out, nullptr, nullptr, 1.0f, 1024, 0);
}

// round 15
// speedup vs baseline: 2.7036x; 1.0216x over previous
#include <cuda_runtime.h>
#include <cuda_bf16.h>
#include <cstdint>
#include <cstddef>

#define D_MODELC 1024
#define NHEADC   16
#define DKC      64
#define SEQC     2048
#define BATCHC   2
#define GKC      1024

// ---------------- device scratch (allocation-free) ----------------
__device__ int g_flags[BATCHC * 32 * 32];

__device__ __nv_bfloat16 g_inhi[3 * 4096 * 1024];
__device__ __nv_bfloat16 g_inlo[3 * 4096 * 1024];
__device__ __nv_bfloat16 g_whi[4 * 1024 * 1024];
__device__ __nv_bfloat16 g_wlo[4 * 1024 * 1024];
__device__ __nv_bfloat16 g_qhi[BATCHC * NHEADC * SEQC * DKC];
__device__ __nv_bfloat16 g_qlo[BATCHC * NHEADC * SEQC * DKC];
__device__ __nv_bfloat16 g_khi[BATCHC * NHEADC * SEQC * DKC];
__device__ __nv_bfloat16 g_klo[BATCHC * NHEADC * SEQC * DKC];
__device__ __nv_bfloat16 g_vhi[BATCHC * NHEADC * SEQC * DKC];
__device__ __nv_bfloat16 g_vlo[BATCHC * NHEADC * SEQC * DKC];
__device__ __nv_bfloat16 g_chi[4096 * 1024];
__device__ __nv_bfloat16 g_clo[4096 * 1024];

// ---------------- helpers ----------------
__device__ __forceinline__ uint32_t smem_u32(const void* p) {
    uint32_t a;
    asm("{ .reg .u64 t; cvta.to.shared.u64 t, %1; cvt.u32.u64 %0, t; }" : "=r"(a) : "l"(p));
    return a;
}
#define LDSM_X4(R, addr) \
    asm volatile("ldmatrix.sync.aligned.m8n8.x4.shared.b16 {%0,%1,%2,%3}, [%4];" \
        : "=r"((R)[0]), "=r"((R)[1]), "=r"((R)[2]), "=r"((R)[3]) : "r"(addr))
#define LDSM_X4_T(R, addr) \
    asm volatile("ldmatrix.sync.aligned.m8n8.x4.trans.shared.b16 {%0,%1,%2,%3}, [%4];" \
        : "=r"((R)[0]), "=r"((R)[1]), "=r"((R)[2]), "=r"((R)[3]) : "r"(addr))
#define MMA16816(C, A, B0, B1) \
    asm volatile("mma.sync.aligned.m16n8k16.row.col.f32.bf16.bf16.f32 " \
        "{%0,%1,%2,%3}, {%4,%5,%6,%7}, {%8,%9}, {%0,%1,%2,%3};" \
        : "+f"((C)[0]), "+f"((C)[1]), "+f"((C)[2]), "+f"((C)[3]) \
        : "r"((A)[0]), "r"((A)[1]), "r"((A)[2]), "r"((A)[3]), "r"(B0), "r"(B1))
#define CP_ASYNC16(saddr, gptr) \
    asm volatile("cp.async.cg.shared.global [%0], [%1], 16;" :: "r"(saddr), "l"(gptr) : "memory")
#define CP_COMMIT() asm volatile("cp.async.commit_group;" ::: "memory")
#define CP_WAIT1()  asm volatile("cp.async.wait_group 1;" ::: "memory")
#define CP_WAIT0()  asm volatile("cp.async.wait_group 0;" ::: "memory")

__device__ __forceinline__ uint32_t pack2bf(float a, float b) {
    __nv_bfloat162 t = __floats2bfloat162_rn(a, b);
    return *(uint32_t*)&t;
}

// ---------------- fast exp (FMA pipe) ----------------
__device__ __forceinline__ float fast_exp(float x) {
    x = fmaxf(x, -87.0f);
    float t  = fmaf(x, 1.4426950408889634f, 12582912.0f);
    int   n  = __float_as_int(t) - 0x4B400000;
    float fn = t - 12582912.0f;
    float f  = fmaf(fn, -0.693359375f, x);
    f        = fmaf(fn,  2.12194899e-4f, f);
    float p  = 8.33333377e-3f;
    p = fmaf(p, f, 4.16666679e-2f);
    p = fmaf(p, f, 0.16666667f);
    p = fmaf(p, f, 0.5f);
    p = fmaf(p, f, 1.0f);
    p = fmaf(p, f, 1.0f);
    return __int_as_float(__float_as_int(p) + (n << 23));
}

// ---------------- fp32 -> bf16 hi/lo split (inputs) ----------------
__global__ void __launch_bounds__(256)
cvt_in_kernel(const float* __restrict__ q, const float* __restrict__ k, const float* __restrict__ v,
              __nv_bfloat16* __restrict__ inhi, __nv_bfloat16* __restrict__ inlo)
{
    const int t = blockIdx.y;
    const int i = blockIdx.x * blockDim.x + threadIdx.x;
    const int n4 = (4096 * 1024) / 4;
    if (i >= n4) return;
    const float* src = (t == 0) ? q : (t == 1) ? k : v;
    __nv_bfloat16* hi = inhi + (size_t)t * 4096 * 1024;
    __nv_bfloat16* lo = inlo + (size_t)t * 4096 * 1024;
    float4 x = ((const float4*)src)[i];
    __nv_bfloat16 h0 = __float2bfloat16(x.x);
    __nv_bfloat16 h1 = __float2bfloat16(x.y);
    __nv_bfloat16 h2 = __float2bfloat16(x.z);
    __nv_bfloat16 h3 = __float2bfloat16(x.w);
    __nv_bfloat162* H = (__nv_bfloat162*)hi;
    __nv_bfloat162* L = (__nv_bfloat162*)lo;
    H[i * 2]     = __nv_bfloat162(h0, h1);
    H[i * 2 + 1] = __nv_bfloat162(h2, h3);
    L[i * 2]     = __nv_bfloat162(__float2bfloat16(x.x - __bfloat162float(h0)),
                                  __float2bfloat16(x.y - __bfloat162float(h1)));
    L[i * 2 + 1] = __nv_bfloat162(__float2bfloat16(x.z - __bfloat162float(h2)),
                                  __float2bfloat16(x.w - __bfloat162float(h3)));
}

// ---------------- fp32 -> bf16 hi/lo split (weights) ----------------
__global__ void __launch_bounds__(256)
cvt_w_kernel(const float* __restrict__ wq, const float* __restrict__ wk,
             const float* __restrict__ wv, const float* __restrict__ wo,
             __nv_bfloat16* __restrict__ whi, __nv_bfloat16* __restrict__ wlo)
{
    const int w = blockIdx.y;
    const int i = blockIdx.x * blockDim.x + threadIdx.x;
    const int n4 = (1024 * 1024) / 4;
    if (i >= n4) return;
    const float* src = (w == 0) ? wq : (w == 1) ? wk : (w == 2) ? wv : wo;
    __nv_bfloat16* hi = whi + (size_t)w * 1024 * 1024;
    __nv_bfloat16* lo = wlo + (size_t)w * 1024 * 1024;
    float4 x = ((const float4*)src)[i];
    __nv_bfloat16 h0 = __float2bfloat16(x.x);
    __nv_bfloat16 h1 = __float2bfloat16(x.y);
    __nv_bfloat16 h2 = __float2bfloat16(x.z);
    __nv_bfloat16 h3 = __float2bfloat16(x.w);
    __nv_bfloat162* H = (__nv_bfloat162*)hi;
    __nv_bfloat162* L = (__nv_bfloat162*)lo;
    H[i * 2]     = __nv_bfloat162(h0, h1);
    H[i * 2 + 1] = __nv_bfloat162(h2, h3);
    L[i * 2]     = __nv_bfloat162(__float2bfloat16(x.x - __bfloat162float(h0)),
                                  __float2bfloat16(x.y - __bfloat162float(h1)));
    L[i * 2 + 1] = __nv_bfloat162(__float2bfloat16(x.z - __bfloat162float(h2)),
                                  __float2bfloat16(x.w - __bfloat162float(h3)));
}

// ---------------- mask prescan ----------------
__global__ void __launch_bounds__(256)
prescan_kernel(const unsigned char* __restrict__ am,
               const unsigned char* __restrict__ kpm,
               int* __restrict__ flags)
{
    const int kt = blockIdx.x, qt = blockIdx.y, b = blockIdx.z;
    const int tid = threadIdx.x;
    unsigned v = 0;
    {
        int q = qt * 64 + (tid >> 2);
        const uint4* p = (const uint4*)(am + ((size_t)(b * SEQC + q)) * SEQC + kt * 64) + (tid & 3);
        uint4 u = *p;
        v = u.x | u.y | u.z | u.w;
    }
    if (tid < 4) {
        const uint4* p = (const uint4*)(kpm + (size_t)b * SEQC + kt * 64) + tid;
        uint4 u = *p;
        v |= u.x | u.y | u.z | u.w;
    }
    #pragma unroll
    for (int off = 16; off >= 1; off >>= 1)
        v |= __shfl_xor_sync(0xffffffffu, v, off);
    __shared__ unsigned wv[8];
    if ((tid & 31) == 0) wv[tid >> 5] = v;
    __syncthreads();
    if (tid == 0) {
        unsigned r = 0;
        #pragma unroll
        for (int w = 0; w < 8; ++w) r |= wv[w];
        flags[(b * 32 + qt) * 32 + kt] = r ? 1 : 0;
    }
}

// ---------------- GEMM body: BK=32 2-stage cp.async, fragments loaded up-front ----------------
#define TSTR 40
#define G_TILE_ELT (128 * TSTR)
#define G_STAGE_ELT (4 * G_TILE_ELT)
#define TCG_SMEM_BYTES (2 * G_STAGE_ELT * 2)   // 81920 B

__device__ __forceinline__ void gemm_body(
    const __nv_bfloat16* __restrict__ Ahi, const __nv_bfloat16* __restrict__ Alo,
    const __nv_bfloat16* __restrict__ Bhi, const __nv_bfloat16* __restrict__ Blo,
    const float* __restrict__ bias, float* __restrict__ Y,
    __nv_bfloat16* __restrict__ Yhi, __nv_bfloat16* __restrict__ Ylo,
    float scale, int N, int mode, int m0, int n0, uint32_t us)
{
    const int tid  = threadIdx.x;
    const int wid  = tid >> 5, lane = tid & 31;
    const int wm   = wid >> 2, wn = wid & 3;

    const int r = tid >> 1, hf = tid & 1;
    const size_t a_off = (size_t)(m0 + r) * GKC + hf * 16;
    const size_t b_off = (size_t)(n0 + r) * GKC + hf * 16;
    const uint32_t sto = (uint32_t)(r * TSTR + hf * 16);

    const int a_row  = wm * 64 + (lane & 15);
    const int a_coff = (lane >> 4) << 3;
    const int b_row  = wn * 32 + (lane & 7) + ((lane >> 4) << 3);
    const int b_koff = ((lane >> 3) & 1) << 3;

    float acc[4][4][4] = {};

    auto load_stage = [&](int kt, int s) {
        const int k0 = kt * 32;
        const uint32_t sb = us + (uint32_t)(s * G_STAGE_ELT) * 2;
        #pragma unroll
        for (int c = 0; c < 2; ++c) {
            uint32_t so = (sto + c * 8) * 2;
            CP_ASYNC16(sb + 0 * G_TILE_ELT * 2 + so, Ahi + a_off + k0 + c * 8);
            CP_ASYNC16(sb + 1 * G_TILE_ELT * 2 + so, Alo + a_off + k0 + c * 8);
            CP_ASYNC16(sb + 2 * G_TILE_ELT * 2 + so, Bhi + b_off + k0 + c * 8);
            CP_ASYNC16(sb + 3 * G_TILE_ELT * 2 + so, Blo + b_off + k0 + c * 8);
        }
        CP_COMMIT();
    };

    load_stage(0, 0);
    for (int kt = 0; kt < GKC / 32; ++kt) {
        if (kt + 1 < GKC / 32) { load_stage(kt + 1, (kt + 1) & 1); CP_WAIT1(); }
        else                   { CP_WAIT0(); }
        __syncthreads();

        const uint32_t sb = us + (uint32_t)((kt & 1) * G_STAGE_ELT) * 2;
        const uint32_t uAh = sb, uAl = sb + G_TILE_ELT * 2;
        const uint32_t uBh = sb + 2 * G_TILE_ELT * 2, uBl = sb + 3 * G_TILE_ELT * 2;

        #pragma unroll
        for (int ks = 0; ks < 2; ++ks) {
            const int kc = ks * 16;
            uint32_t Ah[4][4], Al[4][4], Bh2[2][4], Bl2[2][4];
            // all fragment loads up front -> one uninterrupted MMA run
            #pragma unroll
            for (int mt = 0; mt < 4; ++mt)
                LDSM_X4(Ah[mt], uAh + ((a_row + mt * 16) * TSTR + kc + a_coff) * 2);
            #pragma unroll
            for (int mt = 0; mt < 4; ++mt)
                LDSM_X4(Al[mt], uAl + ((a_row + mt * 16) * TSTR + kc + a_coff) * 2);
            #pragma unroll
            for (int nt2 = 0; nt2 < 2; ++nt2) {
                LDSM_X4(Bh2[nt2], uBh + ((b_row + nt2 * 16) * TSTR + kc + b_koff) * 2);
                LDSM_X4(Bl2[nt2], uBl + ((b_row + nt2 * 16) * TSTR + kc + b_koff) * 2);
            }
            #pragma unroll
            for (int mt = 0; mt < 4; ++mt)
                #pragma unroll
                for (int nt = 0; nt < 4; ++nt)
                    MMA16816(acc[mt][nt], Ah[mt], Bh2[nt >> 1][(nt & 1) * 2], Bh2[nt >> 1][(nt & 1) * 2 + 1]);
            #pragma unroll
            for (int mt = 0; mt < 4; ++mt)
                #pragma unroll
                for (int nt = 0; nt < 4; ++nt)
                    MMA16816(acc[mt][nt], Ah[mt], Bl2[nt >> 1][(nt & 1) * 2], Bl2[nt >> 1][(nt & 1) * 2 + 1]);
            #pragma unroll
            for (int mt = 0; mt < 4; ++mt)
                #pragma unroll
                for (int nt = 0; nt < 4; ++nt)
                    MMA16816(acc[mt][nt], Al[mt], Bh2[nt >> 1][(nt & 1) * 2], Bh2[nt >> 1][(nt & 1) * 2 + 1]);
        }
        __syncthreads();
    }

    const int er = lane >> 2, ec = (lane & 3) * 2;
    #pragma unroll
    for (int mt = 0; mt < 4; ++mt) {
        #pragma unroll
        for (int nt = 0; nt < 4; ++nt) {
            int col  = n0 + wn * 32 + nt * 8 + ec;
            float b0 = __ldg(&bias[col]), b1 = __ldg(&bias[col + 1]);
            #pragma unroll
            for (int half = 0; half < 2; ++half) {
                int m = m0 + wm * 64 + mt * 16 + er + half * 8;
                float vx = (acc[mt][nt][half * 2]     + b0) * scale;
                float vy = (acc[mt][nt][half * 2 + 1] + b1) * scale;
                if (mode == 2) {
                    int bb = m >> 11, s = m & 2047;
                    int hh = col >> 6, dk = col & 63;
                    size_t idx = (((size_t)(bb * NHEADC + hh) * SEQC) + s) * DKC + dk;
                    __nv_bfloat16 hx = __float2bfloat16(vx), hy = __float2bfloat16(vy);
                    *(__nv_bfloat162*)&Yhi[idx] = __nv_bfloat162(hx, hy);
                    *(__nv_bfloat162*)&Ylo[idx] = __nv_bfloat162(
                        __float2bfloat16(vx - __bfloat162float(hx)),
                        __float2bfloat16(vy - __bfloat162float(hy)));
                } else {
                    *(float2*)&Y[(size_t)m * N + col] = make_float2(vx, vy);
                }
            }
        }
    }
}

// fused QKV projections: blockIdx.z selects which GEMM
__global__ void __launch_bounds__(256, 2)
tc_gemm_qkv_kernel(const __nv_bfloat16* __restrict__ inhi, const __nv_bfloat16* __restrict__ inlo,
                   const __nv_bfloat16* __restrict__ whi,  const __nv_bfloat16* __restrict__ wlo,
                   const float* __restrict__ bq, const float* __restrict__ bk, const float* __restrict__ bv,
                   __nv_bfloat16* __restrict__ qhi, __nv_bfloat16* __restrict__ qlo,
                   __nv_bfloat16* __restrict__ khi, __nv_bfloat16* __restrict__ klo,
                   __nv_bfloat16* __restrict__ vhi, __nv_bfloat16* __restrict__ vlo)
{
    extern __shared__ __align__(16) __nv_bfloat16 smem[];
    const int g = blockIdx.z;
    const size_t IN_N = (size_t)4096 * 1024, W_N = (size_t)1024 * 1024;
    const __nv_bfloat16* Ah = inhi + g * IN_N;
    const __nv_bfloat16* Al = inlo + g * IN_N;
    const __nv_bfloat16* Bh = whi + g * W_N;
    const __nv_bfloat16* Bl = wlo + g * W_N;
    const float* bias = (g == 0) ? bq : (g == 1) ? bk : bv;
    __nv_bfloat16* Yh = (g == 0) ? qhi : (g == 1) ? khi : vhi;
    __nv_bfloat16* Yl = (g == 0) ? qlo : (g == 1) ? klo : vlo;
    float scale = (g == 0) ? 0.125f : 1.0f;
    gemm_body(Ah, Al, Bh, Bl, bias, nullptr, Yh, Yl, scale, 1024, 2,
              blockIdx.y * 128, blockIdx.x * 128, smem_u32(smem));
}

// single GEMM (output projection)
__global__ void __launch_bounds__(256, 2)
tc_gemm_kernel(const __nv_bfloat16* __restrict__ Ahi, const __nv_bfloat16* __restrict__ Alo,
               const __nv_bfloat16* __restrict__ Bhi, const __nv_bfloat16* __restrict__ Blo,
               const float* __restrict__ bias, float* __restrict__ Y)
{
    extern __shared__ __align__(16) __nv_bfloat16 smem[];
    gemm_body(Ahi, Alo, Bhi, Blo, bias, Y, nullptr, nullptr, 1.0f, 1024, 0,
              blockIdx.y * 128, blockIdx.x * 128, smem_u32(smem));
}

// ---------------- flash attention on mma.sync + cp.async 2-stage K/V pipeline ----------------
#define ASTR 72
#define A_TILE_ELT (64 * ASTR)
#define A_STAGE_ELT (4 * A_TILE_ELT)
#define ATTN_SMEM_BYTES (2 * A_STAGE_ELT * 2)
__global__ void __launch_bounds__(256)
attn_kernel(const __nv_bfloat16* __restrict__ Qhi, const __nv_bfloat16* __restrict__ Qlo,
            const __nv_bfloat16* __restrict__ Khi, const __nv_bfloat16* __restrict__ Klo,
            const __nv_bfloat16* __restrict__ Vhi, const __nv_bfloat16* __restrict__ Vlo,
            const unsigned char* __restrict__ am,
            const unsigned char* __restrict__ kpm,
            const int* __restrict__ flags,
            __nv_bfloat16* __restrict__ ctxhi, __nv_bfloat16* __restrict__ ctxlo)
{
    extern __shared__ __align__(16) __nv_bfloat16 smem[];
    const uint32_t us = smem_u32(smem);

    const int qt = blockIdx.x;
    const int bh = blockIdx.y;
    const int b  = bh >> 4;
    const int h  = bh & 15;
    const int tid = threadIdx.x;
    const int wid = tid >> 5, lane = tid & 31;
    const int er = lane >> 2, ec = (lane & 3) * 2;

    const size_t qbase = ((size_t)bh * SEQC + qt * 128) * DKC;
    const size_t kvbase = (size_t)bh * SEQC * DKC;

    {
        int r = tid >> 1, hf = tid & 1;
        #pragma unroll
        for (int u = 0; u < 4; ++u) {
            int c = hf * 4 + u;
            uint32_t so = (uint32_t)(r * ASTR + c * 8) * 2;
            CP_ASYNC16(us + so,                     Qhi + qbase + (size_t)r * DKC + c * 8);
            CP_ASYNC16(us + 128 * ASTR * 2 + so,    Qlo + qbase + (size_t)r * DKC + c * 8);
        }
        CP_COMMIT(); CP_WAIT0();
    }
    __syncthreads();

    uint32_t Qh[4][4], Ql[4][4];
    {
        const int a_row  = wid * 16 + (lane & 15);
        const int a_coff = (lane >> 4) << 3;
        #pragma unroll
        for (int ks = 0; ks < 4; ++ks) {
            LDSM_X4(Qh[ks], us + (a_row * ASTR + ks * 16 + a_coff) * 2);
            LDSM_X4(Ql[ks], us + (128 * ASTR + a_row * ASTR + ks * 16 + a_coff) * 2);
        }
    }
    __syncthreads();

    const int b_row  = (lane & 7) + ((lane >> 4) << 3);
    const int b_koff = ((lane >> 3) & 1) << 3;
    const int v_row  = (lane & 7) + (((lane >> 3) & 1) << 3);
    const int v_noff = (lane >> 4) << 3;

    auto load_kv = [&](int kt, int s) {
        int r2 = tid >> 2, qc = tid & 3;
        const size_t g = kvbase + (size_t)(kt * 64 + r2) * DKC;
        const uint32_t sb = us + (uint32_t)(s * A_STAGE_ELT) * 2;
        #pragma unroll
        for (int u = 0; u < 2; ++u) {
            int c = qc * 2 + u;
            uint32_t so = (uint32_t)(r2 * ASTR + c * 8) * 2;
            CP_ASYNC16(sb + 0 * A_TILE_ELT * 2 + so, Khi + g + c * 8);
            CP_ASYNC16(sb + 1 * A_TILE_ELT * 2 + so, Klo + g + c * 8);
            CP_ASYNC16(sb + 2 * A_TILE_ELT * 2 + so, Vhi + g + c * 8);
            CP_ASYNC16(sb + 3 * A_TILE_ELT * 2 + so, Vlo + g + c * 8);
        }
        CP_COMMIT();
    };

    float oacc[8][4] = {};
    float m0r = -1e30f, m1r = -1e30f, l0r = 0.f, l1r = 0.f;

    load_kv(0, 0);
    for (int kt = 0; kt < SEQC / 64; ++kt) {
        if (kt + 1 < SEQC / 64) { load_kv(kt + 1, (kt + 1) & 1); CP_WAIT1(); }
        else                    { CP_WAIT0(); }
        __syncthreads();

        const uint32_t sb = us + (uint32_t)((kt & 1) * A_STAGE_ELT) * 2;
        const uint32_t uKh = sb, uKl = sb + A_TILE_ELT * 2;
        const uint32_t uVh = sb + 2 * A_TILE_ELT * 2, uVl = sb + 3 * A_TILE_ELT * 2;

        float s[8][4] = {};
        #pragma unroll
        for (int ks = 0; ks < 4; ++ks) {
            const int kc = ks * 16;
            uint32_t KB[4][4];
            #pragma unroll
            for (int g = 0; g < 4; ++g)
                LDSM_X4(KB[g], uKh + ((g * 16 + b_row) * ASTR + kc + b_koff) * 2);
            #pragma unroll
            for (int nt = 0; nt < 8; ++nt)
                MMA16816(s[nt], Qh[ks], KB[nt >> 1][(nt & 1) * 2], KB[nt >> 1][(nt & 1) * 2 + 1]);
            #pragma unroll
            for (int nt = 0; nt < 8; ++nt)
                MMA16816(s[nt], Ql[ks], KB[nt >> 1][(nt & 1) * 2], KB[nt >> 1][(nt & 1) * 2 + 1]);
            #pragma unroll
            for (int g = 0; g < 4; ++g)
                LDSM_X4(KB[g], uKl + ((g * 16 + b_row) * ASTR + kc + b_koff) * 2);
            #pragma unroll
            for (int nt = 0; nt < 8; ++nt)
                MMA16816(s[nt], Qh[ks], KB[nt >> 1][(nt & 1) * 2], KB[nt >> 1][(nt & 1) * 2 + 1]);
        }

        int fl = flags[(b * 32 + qt * 2) * 32 + kt] | flags[(b * 32 + qt * 2 + 1) * 32 + kt];
        if (fl) {
            int q0 = qt * 128 + wid * 16 + er;
            #pragma unroll
            for (int nt = 0; nt < 8; ++nt) {
                int kg = kt * 64 + nt * 8 + ec;
                #pragma unroll
                for (int c = 0; c < 4; ++c) {
                    int qg = q0 + (c >> 1) * 8;
                    int kk = kg + (c & 1);
                    if (am[((size_t)(b * SEQC + qg)) * SEQC + kk] | kpm[b * SEQC + kk])
                        s[nt][c] = -1e30f;
                }
            }
        }

        float mx0 = -1e30f, mx1 = -1e30f;
        #pragma unroll
        for (int nt = 0; nt < 8; ++nt) {
            mx0 = fmaxf(mx0, fmaxf(s[nt][0], s[nt][1]));
            mx1 = fmaxf(mx1, fmaxf(s[nt][2], s[nt][3]));
        }
        mx0 = fmaxf(mx0, __shfl_xor_sync(0xffffffffu, mx0, 1));
        mx0 = fmaxf(mx0, __shfl_xor_sync(0xffffffffu, mx0, 2));
        mx1 = fmaxf(mx1, __shfl_xor_sync(0xffffffffu, mx1, 1));
        mx1 = fmaxf(mx1, __shfl_xor_sync(0xffffffffu, mx1, 2));

        float mn0 = fmaxf(m0r, mx0), mn1 = fmaxf(m1r, mx1);
        float al0 = fast_exp(m0r - mn0), al1 = fast_exp(m1r - mn1);
        m0r = mn0; m1r = mn1;

        float sum0 = 0.f, sum1 = 0.f;
        #pragma unroll
        for (int nt = 0; nt < 8; ++nt) {
            float p0 = fast_exp(s[nt][0] - mn0); if (s[nt][0] <= -1e29f) p0 = 0.f;
            float p1 = fast_exp(s[nt][1] - mn0); if (s[nt][1] <= -1e29f) p1 = 0.f;
            float p2 = fast_exp(s[nt][2] - mn1); if (s[nt][2] <= -1e29f) p2 = 0.f;
            float p3 = fast_exp(s[nt][3] - mn1); if (s[nt][3] <= -1e29f) p3 = 0.f;
            s[nt][0] = p0; s[nt][1] = p1; s[nt][2] = p2; s[nt][3] = p3;
            sum0 += p0 + p1; sum1 += p2 + p3;
        }
        sum0 += __shfl_xor_sync(0xffffffffu, sum0, 1);
        sum0 += __shfl_xor_sync(0xffffffffu, sum0, 2);
        sum1 += __shfl_xor_sync(0xffffffffu, sum1, 1);
        sum1 += __shfl_xor_sync(0xffffffffu, sum1, 2);
        l0r = fmaf(l0r, al0, sum0);
        l1r = fmaf(l1r, al1, sum1);
        #pragma unroll
        for (int nt = 0; nt < 8; ++nt) {
            oacc[nt][0] *= al0; oacc[nt][1] *= al0;
            oacc[nt][2] *= al1; oacc[nt][3] *= al1;
        }

        #pragma unroll
        for (int ks = 0; ks < 4; ++ks) {
            const int t0 = 2 * ks, t1 = 2 * ks + 1;
            uint32_t aPh[4], aPl[4];
            {
                float v00 = s[t0][0], v01 = s[t0][1], v02 = s[t0][2], v03 = s[t0][3];
                float v10 = s[t1][0], v11 = s[t1][1], v12 = s[t1][2], v13 = s[t1][3];
                __nv_bfloat16 hh;
                float r00, r01, r02, r03, r10, r11, r12, r13;
                hh = __float2bfloat16(v00); r00 = v00 - __bfloat162float(hh);
                hh = __float2bfloat16(v01); r01 = v01 - __bfloat162float(hh);
                hh = __float2bfloat16(v02); r02 = v02 - __bfloat162float(hh);
                hh = __float2bfloat16(v03); r03 = v03 - __bfloat162float(hh);
                hh = __float2bfloat16(v10); r10 = v10 - __bfloat162float(hh);
                hh = __float2bfloat16(v11); r11 = v11 - __bfloat162float(hh);
                hh = __float2bfloat16(v12); r12 = v12 - __bfloat162float(hh);
                hh = __float2bfloat16(v13); r13 = v13 - __bfloat162float(hh);
                aPh[0] = pack2bf(v00, v01); aPh[1] = pack2bf(v02, v03);
                aPh[2] = pack2bf(v10, v11); aPh[3] = pack2bf(v12, v13);
                aPl[0] = pack2bf(r00, r01); aPl[1] = pack2bf(r02, r03);
                aPl[2] = pack2bf(r10, r11); aPl[3] = pack2bf(r12, r13);
            }
            uint32_t VB[4][4];
            #pragma unroll
            for (int g = 0; g < 4; ++g)
                LDSM_X4_T(VB[g], uVh + ((ks * 16 + v_row) * ASTR + g * 16 + v_noff) * 2);
            #pragma unroll
            for (int nt = 0; nt < 8; ++nt)
                MMA16816(oacc[nt], aPh, VB[nt >> 1][(nt & 1) * 2], VB[nt >> 1][(nt & 1) * 2 + 1]);
            #pragma unroll
            for (int nt = 0; nt < 8; ++nt)
                MMA16816(oacc[nt], aPl, VB[nt >> 1][(nt & 1) * 2], VB[nt >> 1][(nt & 1) * 2 + 1]);
            #pragma unroll
            for (int g = 0; g < 4; ++g)
                LDSM_X4_T(VB[g], uVl + ((ks * 16 + v_row) * ASTR + g * 16 + v_noff) * 2);
            #pragma unroll
            for (int nt = 0; nt < 8; ++nt)
                MMA16816(oacc[nt], aPh, VB[nt >> 1][(nt & 1) * 2], VB[nt >> 1][(nt & 1) * 2 + 1]);
        }
        __syncthreads();
    }

    float r0 = (l0r > 0.f) ? (1.0f / l0r) : 0.f;
    float r1 = (l1r > 0.f) ? (1.0f / l1r) : 0.f;
    const int q0 = qt * 128 + wid * 16 + er;
    #pragma unroll
    for (int nt = 0; nt < 8; ++nt) {
        int col = h * DKC + nt * 8 + ec;
        {
            float vx = oacc[nt][0] * r0, vy = oacc[nt][1] * r0;
            size_t idx = ((size_t)(b * SEQC + q0)) * D_MODELC + col;
            __nv_bfloat16 hx = __float2bfloat16(vx), hy = __float2bfloat16(vy);
            *(__nv_bfloat162*)&ctxhi[idx] = __nv_bfloat162(hx, hy);
            *(__nv_bfloat162*)&ctxlo[idx] = __nv_bfloat162(
                __float2bfloat16(vx - __bfloat162float(hx)),
                __float2bfloat16(vy - __bfloat162float(hy)));
        }
        {
            float vx = oacc[nt][2] * r1, vy = oacc[nt][3] * r1;
            size_t idx = ((size_t)(b * SEQC + q0 + 8)) * D_MODELC + col;
            __nv_bfloat16 hx = __float2bfloat16(vx), hy = __float2bfloat16(vy);
            *(__nv_bfloat162*)&ctxhi[idx] = __nv_bfloat162(hx, hy);
            *(__nv_bfloat162*)&ctxlo[idx] = __nv_bfloat162(
                __float2bfloat16(vx - __bfloat162float(hx)),
                __float2bfloat16(vy - __bfloat162float(hy)));
        }
    }
}

// ---------------- launch ----------------
extern "C" void kernel_launch(void* const* d_in, const int* in_sizes, int n_in,
                              void* d_out, int out_size)
{
    const float* query = (const float*)d_in[0];
    const float* key   = (const float*)d_in[1];
    const float* value = (const float*)d_in[2];
    const unsigned char* am  = (const unsigned char*)d_in[3];
    const unsigned char* kpm = (const unsigned char*)d_in[4];
    const float* Wq = (const float*)d_in[5];
    const float* bq = (const float*)d_in[6];
    const float* Wk = (const float*)d_in[7];
    const float* bk = (const float*)d_in[8];
    const float* Wv = (const float*)d_in[9];
    const float* bv = (const float*)d_in[10];
    const float* Wo = (const float*)d_in[11];
    const float* bo = (const float*)d_in[12];
    float* out = (float*)d_out;

    int* flags;
    __nv_bfloat16 *inhi, *inlo, *whi, *wlo, *chi, *clo;
    __nv_bfloat16 *qhi, *qlo, *khi, *klo, *vhi, *vlo;
    cudaGetSymbolAddress((void**)&flags, g_flags);
    cudaGetSymbolAddress((void**)&inhi,  g_inhi);
    cudaGetSymbolAddress((void**)&inlo,  g_inlo);
    cudaGetSymbolAddress((void**)&whi,   g_whi);
    cudaGetSymbolAddress((void**)&wlo,   g_wlo);
    cudaGetSymbolAddress((void**)&chi,   g_chi);
    cudaGetSymbolAddress((void**)&clo,   g_clo);
    cudaGetSymbolAddress((void**)&qhi,   g_qhi);
    cudaGetSymbolAddress((void**)&qlo,   g_qlo);
    cudaGetSymbolAddress((void**)&khi,   g_khi);
    cudaGetSymbolAddress((void**)&klo,   g_klo);
    cudaGetSymbolAddress((void**)&vhi,   g_vhi);
    cudaGetSymbolAddress((void**)&vlo,   g_vlo);

    static int attr_set = 0;
    if (!attr_set) {
        cudaFuncSetAttribute(attn_kernel, cudaFuncAttributeMaxDynamicSharedMemorySize, ATTN_SMEM_BYTES);
        cudaFuncSetAttribute(tc_gemm_kernel, cudaFuncAttributeMaxDynamicSharedMemorySize, TCG_SMEM_BYTES);
        cudaFuncSetAttribute(tc_gemm_qkv_kernel, cudaFuncAttributeMaxDynamicSharedMemorySize, TCG_SMEM_BYTES);
        attr_set = 1;
    }

    // launch 1: prescan
    dim3 pg(32, 32, 2);
    prescan_kernel<<<pg, 256>>>(am, kpm, flags);

    // launch 2: input conversions
    dim3 ci(4096, 3);
    cvt_in_kernel<<<ci, 256>>>(query, key, value, inhi, inlo);

    // launch 3: weight conversions
    dim3 cw(1024, 4);
    cvt_w_kernel<<<cw, 256>>>(Wq, Wk, Wv, Wo, whi, wlo);

    // launch 4: fused QKV projections (768 CTAs -> dense waves)
    dim3 gq(8, 32, 3);
    tc_gemm_qkv_kernel<<<gq, 256, TCG_SMEM_BYTES>>>(inhi, inlo, whi, wlo, bq, bk, bv,
                                                    qhi, qlo, khi, klo, vhi, vlo);

    // launch 5: attention
    dim3 ag(16, 32);
    attn_kernel<<<ag, 256, ATTN_SMEM_BYTES>>>(qhi, qlo, khi, klo, vhi, vlo, am, kpm, flags, chi, clo);

    // launch 6 (profiled by ncu -s 5 -c 1): output projection
    const size_t W_N = (size_t)1024 * 1024;
    dim3 gg(8, 32);
    tc_gemm_kernel<<<gg, 256, TCG_SMEM_BYTES>>>(chi, clo, whi + 3 * W_N, wlo + 3 * W_N, bo, out);
}